// round 1
// baseline (speedup 1.0000x reference)
#include <cuda_runtime.h>
#include <cstdint>

#define N_AUTHOR 100000
#define N_PAPER  200000
#define N_FIELD  50000
#define N_INST   8000

// ---------------- device scratch (static — no runtime allocation) ----------------
// projected messages per relation, 64 floats per src node, concatenated:
// rel order: writes, rev_writes, cites, has_topic, rev_has_topic, affiliated_with, rev_affiliated_with
// row offsets:      0,     100000,300000,   500000,        700000,          750000,              850000  (total 858000 rows)
__device__ float    g_y[54912000];
// per-relation in-degree of dst, later overwritten in-place with float(1/max(deg,1)) bits
// offsets: 0,200000,300000,500000,550000,750000,758000 (total 858000)
__device__ unsigned g_deg[858000];
// tf32-rounded weights: weight[7,128,64] then self_loop_weight[128,64]
__device__ float    g_w[65536];

static inline int ceil_div(int a, int b) { return (a + b - 1) / b; }

// ---------------- small prep kernels ----------------
__global__ __launch_bounds__(256) void round_weights_kernel(const float* __restrict__ w,
                                                            const float* __restrict__ sw) {
    int i = blockIdx.x * blockDim.x + threadIdx.x;
    if (i < 65536) {
        float v = (i < 57344) ? w[i] : sw[i - 57344];
        unsigned t;
        asm("cvt.rna.tf32.f32 %0, %1;" : "=r"(t) : "f"(v));
        g_w[i] = __uint_as_float(t);
    }
}

__global__ __launch_bounds__(256) void zero_deg_kernel() {
    int i = blockIdx.x * blockDim.x + threadIdx.x;
    if (i < 858000) g_deg[i] = 0u;
}

__global__ __launch_bounds__(256) void count_deg_kernel(const int* __restrict__ dst, int E, int off) {
    int i = blockIdx.x * blockDim.x + threadIdx.x;
    if (i < E) atomicAdd(&g_deg[off + dst[i]], 1u);
}

__global__ __launch_bounds__(256) void inv_deg_kernel() {
    int i = blockIdx.x * blockDim.x + threadIdx.x;
    if (i < 858000) {
        unsigned d = g_deg[i];
        float f = 1.0f / (float)(d > 0u ? d : 1u);
        g_deg[i] = __float_as_uint(f);
    }
}

// ---------------- tf32 tensor-core GEMM: C[M,64] = A[M,128] @ B[128,64] (+bias) ----------------
// 128 threads (4 warps). CTA tile: 64 rows x 64 cols, full K=128.
// Each warp: 16 rows x 64 cols via mma.sync.m16n8k8 tf32.
__global__ __launch_bounds__(128) void gemm_tf32_kernel(const float* __restrict__ A,
                                                        const float* __restrict__ B,
                                                        const float* __restrict__ bias,
                                                        float* __restrict__ C, int M) {
    __shared__ unsigned As[64 * 132];  // 64 rows x 128 cols, padded stride 132 (bank-conflict-free)

    const int tid  = threadIdx.x;
    const int warp = tid >> 5;
    const int lane = tid & 31;
    const int g    = lane >> 2;   // group id 0..7
    const int tig  = lane & 3;    // thread-in-group 0..3
    const int row0 = blockIdx.x * 64;

    // Stage A tile into smem as RNA-rounded tf32. 2 threads per row, 16 float4 each.
    {
        int r  = tid >> 1;
        int cb = (tid & 1) * 64;
        bool valid = (row0 + r) < M;
        const float4* ap = (const float4*)(A + (size_t)(row0 + r) * 128 + cb);
#pragma unroll
        for (int i = 0; i < 16; i++) {
            float4 v = valid ? __ldg(ap + i) : make_float4(0.f, 0.f, 0.f, 0.f);
            unsigned t0, t1, t2, t3;
            asm("cvt.rna.tf32.f32 %0, %1;" : "=r"(t0) : "f"(v.x));
            asm("cvt.rna.tf32.f32 %0, %1;" : "=r"(t1) : "f"(v.y));
            asm("cvt.rna.tf32.f32 %0, %1;" : "=r"(t2) : "f"(v.z));
            asm("cvt.rna.tf32.f32 %0, %1;" : "=r"(t3) : "f"(v.w));
            *((uint4*)&As[r * 132 + cb + i * 4]) = make_uint4(t0, t1, t2, t3);
        }
    }
    __syncthreads();

    float c[8][4];
#pragma unroll
    for (int nb = 0; nb < 8; nb++)
#pragma unroll
        for (int j = 0; j < 4; j++) c[nb][j] = 0.f;

    const int arow = warp * 16;
#pragma unroll
    for (int kc = 0; kc < 16; kc++) {
        const int k0 = kc * 8;
        unsigned a0 = As[(arow + g) * 132 + k0 + tig];
        unsigned a1 = As[(arow + g + 8) * 132 + k0 + tig];
        unsigned a2 = As[(arow + g) * 132 + k0 + tig + 4];
        unsigned a3 = As[(arow + g + 8) * 132 + k0 + tig + 4];
#pragma unroll
        for (int nb = 0; nb < 8; nb++) {
            // B fragment (col frag of k8 x n8): b0 = B[k0+tig][nb*8+g], b1 = B[k0+tig+4][nb*8+g]
            unsigned b0 = __float_as_uint(__ldg(&B[(k0 + tig) * 64 + nb * 8 + g]));
            unsigned b1 = __float_as_uint(__ldg(&B[(k0 + tig + 4) * 64 + nb * 8 + g]));
            asm volatile(
                "mma.sync.aligned.m16n8k8.row.col.f32.tf32.tf32.f32 "
                "{%0,%1,%2,%3}, {%4,%5,%6,%7}, {%8,%9}, {%0,%1,%2,%3};"
                : "+f"(c[nb][0]), "+f"(c[nb][1]), "+f"(c[nb][2]), "+f"(c[nb][3])
                : "r"(a0), "r"(a1), "r"(a2), "r"(a3), "r"(b0), "r"(b1));
        }
    }

    const int r0 = row0 + arow + g;
#pragma unroll
    for (int nb = 0; nb < 8; nb++) {
        int col = nb * 8 + tig * 2;
        float b0v = 0.f, b1v = 0.f;
        if (bias) { b0v = __ldg(&bias[col]); b1v = __ldg(&bias[col + 1]); }
        if (r0 < M)
            *(float2*)&C[(size_t)r0 * 64 + col] = make_float2(c[nb][0] + b0v, c[nb][1] + b1v);
        if (r0 + 8 < M)
            *(float2*)&C[(size_t)(r0 + 8) * 64 + col] = make_float2(c[nb][2] + b0v, c[nb][3] + b1v);
    }
}

// ---------------- edge scatter: out[dst] += y[src] * invdeg[dst] ----------------
// One edge per 16-lane group; each lane moves one float4 (64 floats per edge row).
__global__ __launch_bounds__(256) void scatter_kernel(const float4* __restrict__ y,
                                                      const int* __restrict__ src,
                                                      const int* __restrict__ dst,
                                                      int E, int degoff,
                                                      float* __restrict__ out) {
    int e = blockIdx.x * (blockDim.x >> 4) + (threadIdx.x >> 4);
    if (e >= E) return;
    int l = threadIdx.x & 15;
    int s = __ldg(&src[e]);
    int d = __ldg(&dst[e]);
    float sc = __uint_as_float(__ldg(&g_deg[degoff + d]));
    float4 v = __ldg(&y[(size_t)s * 16 + l]);
    float* p = out + (size_t)d * 64 + l * 4;
    asm volatile("red.global.add.v4.f32 [%0], {%1,%2,%3,%4};"
                 :: "l"(p), "f"(v.x * sc), "f"(v.y * sc), "f"(v.z * sc), "f"(v.w * sc)
                 : "memory");
}

__global__ __launch_bounds__(256) void relu_kernel(float4* __restrict__ out, int n4) {
    int i = blockIdx.x * blockDim.x + threadIdx.x;
    if (i < n4) {
        float4 v = out[i];
        v.x = fmaxf(v.x, 0.f); v.y = fmaxf(v.y, 0.f);
        v.z = fmaxf(v.z, 0.f); v.w = fmaxf(v.w, 0.f);
        out[i] = v;
    }
}

// ---------------- launch ----------------
extern "C" void kernel_launch(void* const* d_in, const int* in_sizes, int n_in,
                              void* d_out, int out_size) {
    const float* x_author = (const float*)d_in[0];
    const float* x_field  = (const float*)d_in[1];
    const float* x_inst   = (const float*)d_in[2];
    const float* x_paper  = (const float*)d_in[3];
    const float* weight   = (const float*)d_in[4];
    const float* selfw    = (const float*)d_in[5];
    const float* bias     = (const float*)d_in[6];

    const int* e_src[7]; const int* e_dst[7]; int E[7];
    for (int r = 0; r < 7; r++) {
        e_src[r] = (const int*)d_in[7 + 2 * r];
        e_dst[r] = (const int*)d_in[8 + 2 * r];
        E[r]     = in_sizes[7 + 2 * r];
    }
    float* out = (float*)d_out;

    float* yb; float* wb;
    cudaGetSymbolAddress((void**)&yb, g_y);
    cudaGetSymbolAddress((void**)&wb, g_w);

    // output row offsets (tuple order: author, field, inst, paper)
    float* out_author = out;
    float* out_field  = out + (size_t)N_AUTHOR * 64;
    float* out_inst   = out + (size_t)(N_AUTHOR + N_FIELD) * 64;
    float* out_paper  = out + (size_t)(N_AUTHOR + N_FIELD + N_INST) * 64;

    static const int DEG_OFF[7] = {0, 200000, 300000, 500000, 550000, 750000, 758000};
    static const int Y_ROW [7] = {0, 100000, 300000, 500000, 700000, 750000, 850000};

    // 1) round weights to tf32 (RNA) once per call
    round_weights_kernel<<<256, 256>>>(weight, selfw);

    // 2) degrees
    zero_deg_kernel<<<ceil_div(858000, 256), 256>>>();
    for (int r = 0; r < 7; r++)
        count_deg_kernel<<<ceil_div(E[r], 256), 256>>>(e_dst[r], E[r], DEG_OFF[r]);
    inv_deg_kernel<<<ceil_div(858000, 256), 256>>>();

    // 3) relation projections: y_r = x_srcType @ W[r]
    const float* proj_A[7] = {x_author, x_paper, x_paper, x_paper, x_field, x_author, x_inst};
    const int    proj_M[7] = {N_AUTHOR, N_PAPER, N_PAPER, N_PAPER, N_FIELD, N_AUTHOR, N_INST};
    for (int r = 0; r < 7; r++)
        gemm_tf32_kernel<<<ceil_div(proj_M[r], 64), 128>>>(
            proj_A[r], wb + r * 8192, nullptr, yb + (size_t)Y_ROW[r] * 64, proj_M[r]);

    // 4) self-loop + bias written straight into d_out (scatter accumulates on top)
    gemm_tf32_kernel<<<ceil_div(N_AUTHOR, 64), 128>>>(x_author, wb + 57344, bias, out_author, N_AUTHOR);
    gemm_tf32_kernel<<<ceil_div(N_FIELD,  64), 128>>>(x_field,  wb + 57344, bias, out_field,  N_FIELD);
    gemm_tf32_kernel<<<ceil_div(N_INST,   64), 128>>>(x_inst,   wb + 57344, bias, out_inst,   N_INST);
    gemm_tf32_kernel<<<ceil_div(N_PAPER,  64), 128>>>(x_paper,  wb + 57344, bias, out_paper,  N_PAPER);

    // 5) normalized scatter-add per relation
    float* scat_out[7] = {out_paper, out_author, out_paper, out_field, out_paper, out_inst, out_author};
    for (int r = 0; r < 7; r++)
        scatter_kernel<<<ceil_div(E[r], 16), 256>>>(
            (const float4*)(yb + (size_t)Y_ROW[r] * 64), e_src[r], e_dst[r],
            E[r], DEG_OFF[r], scat_out[r]);

    // 6) ReLU over the full output
    int n4 = (N_AUTHOR + N_FIELD + N_INST + N_PAPER) * 64 / 4;  // 5,728,000
    relu_kernel<<<ceil_div(n4, 256), 256>>>((float4*)out, n4);
}

// round 3
// speedup vs baseline: 1.5507x; 1.5507x over previous
#include <cuda_runtime.h>
#include <cstdint>

#define N_AUTHOR 100000
#define N_PAPER  200000
#define N_FIELD  50000
#define N_INST   8000
// combined node space (== output row order): author[0,1e5) field[1e5,1.5e5) inst[1.5e5,1.58e5) paper[1.58e5,3.58e5)
#define N_NODES  358000
#define EDGE_CAP 5100000

// ---------------- static device scratch ----------------
__device__ float    g_y[54912000];       // projected messages, rows indexed by Y_ROW[rel]+src
__device__ unsigned g_deg[858000];       // per-rel dst degree -> invdeg float bits (in place)
__device__ int      g_cdeg[N_NODES];     // combined degree per node
__device__ int      g_off[N_NODES + 1];  // CSR offsets
__device__ int      g_cur[N_NODES];      // placement cursors
__device__ int      g_part[512];         // scan partials
__device__ uint2    g_perm[EDGE_CAP];    // per-edge payload: (y_row, invdeg bits)
__device__ float    g_w[90112];          // tf32 weights, 11 blocks of [128x64] row-major

static inline int ceil_div(int a, int b) { return (a + b - 1) / b; }

// ---------------- prep kernels ----------------
// 11 column blocks of 64: [W0 W5 self | W1 W2 W3 self | W4 self | W6 self]
__global__ __launch_bounds__(256) void pack_w_kernel(const float* __restrict__ w,
                                                     const float* __restrict__ sw) {
    int i = blockIdx.x * 256 + threadIdx.x;
    if (i >= 90112) return;
    const int BLK_SRC[11] = {0, 5, 7, 1, 2, 3, 7, 4, 7, 6, 7};
    int blk = i >> 13, r = i & 8191;
    int s = BLK_SRC[blk];
    float v = (s == 7) ? sw[r] : w[s * 8192 + r];
    unsigned t;
    asm("cvt.rna.tf32.f32 %0, %1;" : "=r"(t) : "f"(v));
    g_w[i] = __uint_as_float(t);
}

__global__ __launch_bounds__(256) void zero_kernel() {
    int i = blockIdx.x * 256 + threadIdx.x;
    if (i < 858000) g_deg[i] = 0u;
    if (i < N_NODES) g_cur[i] = 0;
}

__global__ __launch_bounds__(256) void count_deg_kernel(const int* __restrict__ dst, int E, int off) {
    int i = blockIdx.x * 256 + threadIdx.x;
    if (i < E) atomicAdd(&g_deg[off + dst[i]], 1u);
}

// combined degree per node (reads raw counts — must run before inv_deg)
__global__ __launch_bounds__(256) void cdeg_kernel() {
    int i = blockIdx.x * 256 + threadIdx.x;
    if (i >= N_NODES) return;
    int c;
    if (i < 100000)      c = (int)(g_deg[200000 + i] + g_deg[758000 + i]);          // author: rel1, rel6
    else if (i < 150000) c = (int)g_deg[500000 + (i - 100000)];                      // field: rel3
    else if (i < 158000) c = (int)g_deg[750000 + (i - 150000)];                      // inst:  rel5
    else { int d = i - 158000; c = (int)(g_deg[d] + g_deg[300000 + d] + g_deg[550000 + d]); } // paper
    g_cdeg[i] = c;
}

__global__ __launch_bounds__(256) void inv_deg_kernel() {
    int i = blockIdx.x * 256 + threadIdx.x;
    if (i < 858000) {
        unsigned d = g_deg[i];
        g_deg[i] = __float_as_uint(1.0f / (float)(d > 0u ? d : 1u));
    }
}

// ---------------- prefix scan of g_cdeg (chunk=1024) ----------------
__global__ __launch_bounds__(256) void scan1_kernel() {
    int b = blockIdx.x, t = threadIdx.x;
    int base = b * 1024, s = 0;
#pragma unroll
    for (int k = 0; k < 4; ++k) {
        int i = base + t * 4 + k;
        if (i < N_NODES) s += g_cdeg[i];
    }
    __shared__ int sm[256];
    sm[t] = s; __syncthreads();
    for (int d = 128; d > 0; d >>= 1) { if (t < d) sm[t] += sm[t + d]; __syncthreads(); }
    if (t == 0) g_part[b] = sm[0];
}

__global__ __launch_bounds__(512) void scan2_kernel(int nparts) {
    __shared__ int sm[512];
    int t = threadIdx.x;
    int v = (t < nparts) ? g_part[t] : 0;
    sm[t] = v; __syncthreads();
    for (int d = 1; d < 512; d <<= 1) {
        int x = (t >= d) ? sm[t - d] : 0; __syncthreads();
        sm[t] += x; __syncthreads();
    }
    if (t < nparts) g_part[t] = sm[t] - v;  // exclusive
    if (t == 511) g_off[N_NODES] = sm[511]; // total
}

__global__ __launch_bounds__(1024) void scan3_kernel() {
    int b = blockIdx.x, t = threadIdx.x;
    int i = b * 1024 + t;
    int v = (i < N_NODES) ? g_cdeg[i] : 0;
    __shared__ int sm[1024];
    sm[t] = v; __syncthreads();
    for (int d = 1; d < 1024; d <<= 1) {
        int x = (t >= d) ? sm[t - d] : 0; __syncthreads();
        sm[t] += x; __syncthreads();
    }
    if (i < N_NODES) g_off[i] = g_part[b] + sm[t] - v;
}

// ---------------- edge placement (after inv_deg: scale resolved here) ----------------
__global__ __launch_bounds__(256) void place_kernel(const int* __restrict__ src,
                                                    const int* __restrict__ dst,
                                                    int E, int degoff, int typeBase, int yrowBase) {
    int e = blockIdx.x * 256 + threadIdx.x;
    if (e >= E) return;
    int d = __ldg(&dst[e]);
    int gg = typeBase + d;
    int pos = g_off[gg] + atomicAdd(&g_cur[gg], 1);
    g_perm[pos] = make_uint2((unsigned)(yrowBase + __ldg(&src[e])), g_deg[degoff + d]);
}

// ---------------- fused tf32 GEMM: C[M,64*gridY] = A[M,128] @ blocks ----------------
struct OutPtrs { float* p[4]; };

__global__ __launch_bounds__(256) void gemm_kernel(const float* __restrict__ A,
                                                   const float* __restrict__ Bbase,
                                                   OutPtrs outs, int selfcb,
                                                   const float* __restrict__ bias, int M) {
    __shared__ unsigned Bs[128 * 72];  // stride 72 words: conflict-free frag loads
    const int tid = threadIdx.x, warp = tid >> 5, lane = tid & 31;
    const int g = lane >> 2, tig = lane & 3;
    const int row0 = blockIdx.x * 128;
    const int cb = blockIdx.y;

    // stage this column block's [128x64] tf32 weights (already rounded)
    const float4* bsrc = (const float4*)(Bbase + cb * 8192);
#pragma unroll
    for (int it = 0; it < 8; ++it) {
        int idx = it * 256 + tid;        // 0..2047 float4s
        int k = idx >> 4, j4 = idx & 15;
        float4 v = __ldg(bsrc + idx);
        *(float4*)&Bs[k * 72 + j4 * 4] = v;
    }
    __syncthreads();

    float c[8][4];
#pragma unroll
    for (int nb = 0; nb < 8; nb++)
#pragma unroll
        for (int j = 0; j < 4; j++) c[nb][j] = 0.f;

    const int r0g = row0 + warp * 16 + g;
    const bool v0 = r0g < M, v1 = (r0g + 8) < M;
    const float* A0 = A + (size_t)r0g * 128;
    const float* A1 = A0 + 8 * 128;

#pragma unroll
    for (int kc = 0; kc < 16; ++kc) {
        const int k0 = kc * 8;
        float f0 = v0 ? __ldg(A0 + k0 + tig)     : 0.f;
        float f2 = v0 ? __ldg(A0 + k0 + tig + 4) : 0.f;
        float f1 = v1 ? __ldg(A1 + k0 + tig)     : 0.f;
        float f3 = v1 ? __ldg(A1 + k0 + tig + 4) : 0.f;
        unsigned a0, a1, a2, a3;
        asm("cvt.rna.tf32.f32 %0, %1;" : "=r"(a0) : "f"(f0));
        asm("cvt.rna.tf32.f32 %0, %1;" : "=r"(a1) : "f"(f1));
        asm("cvt.rna.tf32.f32 %0, %1;" : "=r"(a2) : "f"(f2));
        asm("cvt.rna.tf32.f32 %0, %1;" : "=r"(a3) : "f"(f3));

        unsigned b0[8], b1[8];
#pragma unroll
        for (int nb = 0; nb < 8; ++nb) {
            b0[nb] = Bs[(k0 + tig) * 72 + nb * 8 + g];
            b1[nb] = Bs[(k0 + tig + 4) * 72 + nb * 8 + g];
        }
#pragma unroll
        for (int nb = 0; nb < 8; ++nb) {
            asm volatile(
                "mma.sync.aligned.m16n8k8.row.col.f32.tf32.tf32.f32 "
                "{%0,%1,%2,%3}, {%4,%5,%6,%7}, {%8,%9}, {%0,%1,%2,%3};"
                : "+f"(c[nb][0]), "+f"(c[nb][1]), "+f"(c[nb][2]), "+f"(c[nb][3])
                : "r"(a0), "r"(a1), "r"(a2), "r"(a3), "r"(b0[nb]), "r"(b1[nb]));
        }
    }

    float* C = outs.p[cb];
    const bool ab = (cb == selfcb);
#pragma unroll
    for (int nb = 0; nb < 8; ++nb) {
        int col = nb * 8 + tig * 2;
        float b0v = 0.f, b1v = 0.f;
        if (ab) { b0v = __ldg(&bias[col]); b1v = __ldg(&bias[col + 1]); }
        if (v0) *(float2*)&C[(size_t)r0g * 64 + col] =
                    make_float2(c[nb][0] + b0v, c[nb][1] + b1v);
        if (v1) *(float2*)&C[(size_t)(r0g + 8) * 64 + col] =
                    make_float2(c[nb][2] + b0v, c[nb][3] + b1v);
    }
}

// ---------------- CSR accumulate + ReLU: warp per node, float2 per lane ----------------
__global__ __launch_bounds__(256) void accum_kernel(const float2* __restrict__ y2,
                                                    float2* __restrict__ out2) {
    int node = blockIdx.x * 8 + (threadIdx.x >> 5);
    if (node >= N_NODES) return;
    int l = threadIdx.x & 31;
    int s = g_off[node], e = g_off[node + 1];

    float2 acc = make_float2(0.f, 0.f);
    int i = s;
    for (; i + 1 < e; i += 2) {
        uint2 p0 = __ldg(&g_perm[i]);
        uint2 p1 = __ldg(&g_perm[i + 1]);
        float2 va = __ldg(&y2[(size_t)p0.x * 32 + l]);
        float2 vb = __ldg(&y2[(size_t)p1.x * 32 + l]);
        float s0 = __uint_as_float(p0.y), s1 = __uint_as_float(p1.y);
        acc.x += va.x * s0 + vb.x * s1;
        acc.y += va.y * s0 + vb.y * s1;
    }
    if (i < e) {
        uint2 p = __ldg(&g_perm[i]);
        float2 v = __ldg(&y2[(size_t)p.x * 32 + l]);
        float sc = __uint_as_float(p.y);
        acc.x += v.x * sc;
        acc.y += v.y * sc;
    }

    float2 o = out2[(size_t)node * 32 + l];  // self-loop + bias from GEMM
    o.x = fmaxf(o.x + acc.x, 0.f);
    o.y = fmaxf(o.y + acc.y, 0.f);
    out2[(size_t)node * 32 + l] = o;
}

// ---------------- launch ----------------
extern "C" void kernel_launch(void* const* d_in, const int* in_sizes, int n_in,
                              void* d_out, int out_size) {
    const float* x_author = (const float*)d_in[0];
    const float* x_field  = (const float*)d_in[1];
    const float* x_inst   = (const float*)d_in[2];
    const float* x_paper  = (const float*)d_in[3];
    const float* weight   = (const float*)d_in[4];
    const float* selfw    = (const float*)d_in[5];
    const float* bias     = (const float*)d_in[6];

    const int* e_src[7]; const int* e_dst[7]; int E[7];
    for (int r = 0; r < 7; r++) {
        e_src[r] = (const int*)d_in[7 + 2 * r];
        e_dst[r] = (const int*)d_in[8 + 2 * r];
        E[r]     = in_sizes[7 + 2 * r];
    }
    float* out = (float*)d_out;

    float* yb; float* wb;
    cudaGetSymbolAddress((void**)&yb, g_y);
    cudaGetSymbolAddress((void**)&wb, g_w);

    float* out_author = out;
    float* out_field  = out + (size_t)N_AUTHOR * 64;
    float* out_inst   = out + (size_t)(N_AUTHOR + N_FIELD) * 64;
    float* out_paper  = out + (size_t)(N_AUTHOR + N_FIELD + N_INST) * 64;

    static const int DEG_OFF[7]   = {0, 200000, 300000, 500000, 550000, 750000, 758000};
    static const int Y_ROW[7]     = {0, 100000, 300000, 500000, 700000, 750000, 850000};
    static const int TYPE_BASE[7] = {158000, 0, 158000, 100000, 158000, 150000, 0};

    // weights + degree counting + CSR build
    pack_w_kernel<<<ceil_div(90112, 256), 256>>>(weight, selfw);
    zero_kernel<<<ceil_div(858000, 256), 256>>>();
    for (int r = 0; r < 7; r++)
        count_deg_kernel<<<ceil_div(E[r], 256), 256>>>(e_dst[r], E[r], DEG_OFF[r]);
    cdeg_kernel<<<ceil_div(N_NODES, 256), 256>>>();
    inv_deg_kernel<<<ceil_div(858000, 256), 256>>>();
    const int nchunks = ceil_div(N_NODES, 1024);  // 350
    scan1_kernel<<<nchunks, 256>>>();
    scan2_kernel<<<1, 512>>>(nchunks);
    scan3_kernel<<<nchunks, 1024>>>();
    for (int r = 0; r < 7; r++)
        place_kernel<<<ceil_div(E[r], 256), 256>>>(e_src[r], e_dst[r], E[r],
                                                   DEG_OFF[r], TYPE_BASE[r], Y_ROW[r]);

    // fused projections per src type (self-loop block -> d_out with bias)
    {   // author: [W0 | W5 | self]
        OutPtrs o; o.p[0] = yb; o.p[1] = yb + (size_t)750000 * 64; o.p[2] = out_author; o.p[3] = nullptr;
        dim3 grid(ceil_div(N_AUTHOR, 128), 3);
        gemm_kernel<<<grid, 256>>>(x_author, wb + 0 * 8192, o, 2, bias, N_AUTHOR);
    }
    {   // paper: [W1 | W2 | W3 | self]
        OutPtrs o; o.p[0] = yb + (size_t)100000 * 64; o.p[1] = yb + (size_t)300000 * 64;
        o.p[2] = yb + (size_t)500000 * 64; o.p[3] = out_paper;
        dim3 grid(ceil_div(N_PAPER, 128), 4);
        gemm_kernel<<<grid, 256>>>(x_paper, wb + 3 * 8192, o, 3, bias, N_PAPER);
    }
    {   // field: [W4 | self]
        OutPtrs o; o.p[0] = yb + (size_t)700000 * 64; o.p[1] = out_field; o.p[2] = nullptr; o.p[3] = nullptr;
        dim3 grid(ceil_div(N_FIELD, 128), 2);
        gemm_kernel<<<grid, 256>>>(x_field, wb + 7 * 8192, o, 1, bias, N_FIELD);
    }
    {   // inst: [W6 | self]
        OutPtrs o; o.p[0] = yb + (size_t)850000 * 64; o.p[1] = out_inst; o.p[2] = nullptr; o.p[3] = nullptr;
        dim3 grid(ceil_div(N_INST, 128), 2);
        gemm_kernel<<<grid, 256>>>(x_inst, wb + 9 * 8192, o, 1, bias, N_INST);
    }

    // CSR gather-sum + fused ReLU
    accum_kernel<<<ceil_div(N_NODES, 8), 256>>>((const float2*)yb, (float2*)out);
}

// round 4
// speedup vs baseline: 1.6892x; 1.0893x over previous
#include <cuda_runtime.h>
#include <cuda_fp16.h>
#include <cstdint>

#define N_AUTHOR 100000
#define N_PAPER  200000
#define N_FIELD  50000
#define N_INST   8000
// combined node space (== output row order): author[0,1e5) field[1e5,1.5e5) inst[1.5e5,1.58e5) paper[1.58e5,3.58e5)
#define N_NODES  358000
#define EDGE_CAP 5100000

// ---------------- static device scratch ----------------
__device__ unsigned g_y[27456000];       // fp16 messages: 858000 rows x 64 halves (32 uints/row)
__device__ unsigned g_deg[858000];       // per-rel dst degree -> invdeg float bits (in place)
__device__ int      g_cdeg[N_NODES];     // combined degree per node
__device__ int      g_off[N_NODES + 1];  // CSR offsets
__device__ int      g_cur[N_NODES];      // placement cursors
__device__ int      g_part[512];         // scan partials
__device__ uint2    g_perm[EDGE_CAP];    // per-edge payload: (y_row, invdeg bits)
__device__ float    g_w[90112];          // tf32 weights, 11 blocks of [128x64] row-major

__constant__ int c_DEG_OFF[7]   = {0, 200000, 300000, 500000, 550000, 750000, 758000};
__constant__ int c_Y_ROW[7]     = {0, 100000, 300000, 500000, 700000, 750000, 850000};
__constant__ int c_TYPE_BASE[7] = {158000, 0, 158000, 100000, 158000, 150000, 0};

struct EdgeSet {
    const int* src[7];
    const int* dst[7];
    int pre[8];   // exclusive prefix of edge counts, pre[7] = total
};

static inline int ceil_div(int a, int b) { return (a + b - 1) / b; }

// ---------------- prep kernels ----------------
// 11 column blocks of 64: [W0 W5 self | W1 W2 W3 self | W4 self | W6 self]
__global__ __launch_bounds__(256) void pack_w_kernel(const float* __restrict__ w,
                                                     const float* __restrict__ sw) {
    int i = blockIdx.x * 256 + threadIdx.x;
    if (i >= 90112) return;
    const int BLK_SRC[11] = {0, 5, 7, 1, 2, 3, 7, 4, 7, 6, 7};
    int blk = i >> 13, r = i & 8191;
    int s = BLK_SRC[blk];
    float v = (s == 7) ? sw[r] : w[s * 8192 + r];
    unsigned t;
    asm("cvt.rna.tf32.f32 %0, %1;" : "=r"(t) : "f"(v));
    g_w[i] = __uint_as_float(t);
}

__global__ __launch_bounds__(256) void zero_kernel() {
    int i = blockIdx.x * 256 + threadIdx.x;
    if (i < 858000) g_deg[i] = 0u;
    if (i < N_NODES) g_cur[i] = 0;
}

// one fused pass over all 7 relations
__global__ __launch_bounds__(256) void count_deg_kernel(EdgeSet es) {
    int idx = blockIdx.x * 256 + threadIdx.x;
    if (idx >= es.pre[7]) return;
    int r = 0;
#pragma unroll
    for (int k = 1; k < 7; ++k) r += (idx >= es.pre[k]);
    int i = idx - es.pre[r];
    atomicAdd(&g_deg[c_DEG_OFF[r] + __ldg(&es.dst[r][i])], 1u);
}

// combined degree per node (reads raw counts — must run before inv_deg)
__global__ __launch_bounds__(256) void cdeg_kernel() {
    int i = blockIdx.x * 256 + threadIdx.x;
    if (i >= N_NODES) return;
    int c;
    if (i < 100000)      c = (int)(g_deg[200000 + i] + g_deg[758000 + i]);          // author: rel1, rel6
    else if (i < 150000) c = (int)g_deg[500000 + (i - 100000)];                      // field: rel3
    else if (i < 158000) c = (int)g_deg[750000 + (i - 150000)];                      // inst:  rel5
    else { int d = i - 158000; c = (int)(g_deg[d] + g_deg[300000 + d] + g_deg[550000 + d]); } // paper
    g_cdeg[i] = c;
}

__global__ __launch_bounds__(256) void inv_deg_kernel() {
    int i = blockIdx.x * 256 + threadIdx.x;
    if (i < 858000) {
        unsigned d = g_deg[i];
        g_deg[i] = __float_as_uint(1.0f / (float)(d > 0u ? d : 1u));
    }
}

// ---------------- prefix scan of g_cdeg (chunk=1024) ----------------
__global__ __launch_bounds__(256) void scan1_kernel() {
    int b = blockIdx.x, t = threadIdx.x;
    int base = b * 1024, s = 0;
#pragma unroll
    for (int k = 0; k < 4; ++k) {
        int i = base + t * 4 + k;
        if (i < N_NODES) s += g_cdeg[i];
    }
    __shared__ int sm[256];
    sm[t] = s; __syncthreads();
    for (int d = 128; d > 0; d >>= 1) { if (t < d) sm[t] += sm[t + d]; __syncthreads(); }
    if (t == 0) g_part[b] = sm[0];
}

__global__ __launch_bounds__(512) void scan2_kernel(int nparts) {
    __shared__ int sm[512];
    int t = threadIdx.x;
    int v = (t < nparts) ? g_part[t] : 0;
    sm[t] = v; __syncthreads();
    for (int d = 1; d < 512; d <<= 1) {
        int x = (t >= d) ? sm[t - d] : 0; __syncthreads();
        sm[t] += x; __syncthreads();
    }
    if (t < nparts) g_part[t] = sm[t] - v;  // exclusive
    if (t == 511) g_off[N_NODES] = sm[511]; // total
}

__global__ __launch_bounds__(1024) void scan3_kernel() {
    int b = blockIdx.x, t = threadIdx.x;
    int i = b * 1024 + t;
    int v = (i < N_NODES) ? g_cdeg[i] : 0;
    __shared__ int sm[1024];
    sm[t] = v; __syncthreads();
    for (int d = 1; d < 1024; d <<= 1) {
        int x = (t >= d) ? sm[t - d] : 0; __syncthreads();
        sm[t] += x; __syncthreads();
    }
    if (i < N_NODES) g_off[i] = g_part[b] + sm[t] - v;
}

// ---------------- fused edge placement (after inv_deg: scale resolved here) ----------------
__global__ __launch_bounds__(256) void place_kernel(EdgeSet es) {
    int idx = blockIdx.x * 256 + threadIdx.x;
    if (idx >= es.pre[7]) return;
    int r = 0;
#pragma unroll
    for (int k = 1; k < 7; ++k) r += (idx >= es.pre[k]);
    int i = idx - es.pre[r];
    int d = __ldg(&es.dst[r][i]);
    int gg = c_TYPE_BASE[r] + d;
    int pos = g_off[gg] + atomicAdd(&g_cur[gg], 1);
    g_perm[pos] = make_uint2((unsigned)(c_Y_ROW[r] + __ldg(&es.src[r][i])),
                             g_deg[c_DEG_OFF[r] + d]);
}

// ---------------- fused tf32 GEMM: per-src-type, blocks -> fp16 y or f32 out ----------------
struct OutPtrs { void* p[4]; };

__global__ __launch_bounds__(256) void gemm_kernel(const float* __restrict__ A,
                                                   const float* __restrict__ Bbase,
                                                   OutPtrs outs, int selfcb,
                                                   const float* __restrict__ bias, int M) {
    __shared__ unsigned Bs[128 * 72];  // stride 72 words: conflict-free frag loads
    const int tid = threadIdx.x, warp = tid >> 5, lane = tid & 31;
    const int g = lane >> 2, tig = lane & 3;
    const int row0 = blockIdx.x * 128;
    const int cb = blockIdx.y;

    // stage this column block's [128x64] tf32 weights (already rounded)
    const float4* bsrc = (const float4*)(Bbase + cb * 8192);
#pragma unroll
    for (int it = 0; it < 8; ++it) {
        int idx = it * 256 + tid;        // 0..2047 float4s
        int k = idx >> 4, j4 = idx & 15;
        float4 v = __ldg(bsrc + idx);
        *(float4*)&Bs[k * 72 + j4 * 4] = v;
    }
    __syncthreads();

    float c[8][4];
#pragma unroll
    for (int nb = 0; nb < 8; nb++)
#pragma unroll
        for (int j = 0; j < 4; j++) c[nb][j] = 0.f;

    const int r0g = row0 + warp * 16 + g;
    const bool v0 = r0g < M, v1 = (r0g + 8) < M;
    const float* A0 = A + (size_t)r0g * 128;
    const float* A1 = A0 + 8 * 128;

#pragma unroll
    for (int kc = 0; kc < 16; ++kc) {
        const int k0 = kc * 8;
        float f0 = v0 ? __ldg(A0 + k0 + tig)     : 0.f;
        float f2 = v0 ? __ldg(A0 + k0 + tig + 4) : 0.f;
        float f1 = v1 ? __ldg(A1 + k0 + tig)     : 0.f;
        float f3 = v1 ? __ldg(A1 + k0 + tig + 4) : 0.f;
        unsigned a0, a1, a2, a3;
        asm("cvt.rna.tf32.f32 %0, %1;" : "=r"(a0) : "f"(f0));
        asm("cvt.rna.tf32.f32 %0, %1;" : "=r"(a1) : "f"(f1));
        asm("cvt.rna.tf32.f32 %0, %1;" : "=r"(a2) : "f"(f2));
        asm("cvt.rna.tf32.f32 %0, %1;" : "=r"(a3) : "f"(f3));

        unsigned b0[8], b1[8];
#pragma unroll
        for (int nb = 0; nb < 8; ++nb) {
            b0[nb] = Bs[(k0 + tig) * 72 + nb * 8 + g];
            b1[nb] = Bs[(k0 + tig + 4) * 72 + nb * 8 + g];
        }
#pragma unroll
        for (int nb = 0; nb < 8; ++nb) {
            asm volatile(
                "mma.sync.aligned.m16n8k8.row.col.f32.tf32.tf32.f32 "
                "{%0,%1,%2,%3}, {%4,%5,%6,%7}, {%8,%9}, {%0,%1,%2,%3};"
                : "+f"(c[nb][0]), "+f"(c[nb][1]), "+f"(c[nb][2]), "+f"(c[nb][3])
                : "r"(a0), "r"(a1), "r"(a2), "r"(a3), "r"(b0[nb]), "r"(b1[nb]));
        }
    }

    if (cb == selfcb) {
        // self-loop block: f32 + bias straight into d_out
        float* C = (float*)outs.p[cb];
#pragma unroll
        for (int nb = 0; nb < 8; ++nb) {
            int col = nb * 8 + tig * 2;
            float b0v = __ldg(&bias[col]), b1v = __ldg(&bias[col + 1]);
            if (v0) *(float2*)&C[(size_t)r0g * 64 + col] =
                        make_float2(c[nb][0] + b0v, c[nb][1] + b1v);
            if (v1) *(float2*)&C[(size_t)(r0g + 8) * 64 + col] =
                        make_float2(c[nb][2] + b0v, c[nb][3] + b1v);
        }
    } else {
        // message block: fp16 into g_y (32 uints per row)
        unsigned* C = (unsigned*)outs.p[cb];
#pragma unroll
        for (int nb = 0; nb < 8; ++nb) {
            int u = nb * 4 + tig;  // uint column index (2 halves)
            if (v0) {
                __half2 h = __float22half2_rn(make_float2(c[nb][0], c[nb][1]));
                C[(size_t)r0g * 32 + u] = *(unsigned*)&h;
            }
            if (v1) {
                __half2 h = __float22half2_rn(make_float2(c[nb][2], c[nb][3]));
                C[(size_t)(r0g + 8) * 32 + u] = *(unsigned*)&h;
            }
        }
    }
}

// ---------------- CSR accumulate + ReLU: warp per node, half2 per lane ----------------
__global__ __launch_bounds__(256) void accum_kernel(float2* __restrict__ out2) {
    int node = blockIdx.x * 8 + (threadIdx.x >> 5);
    if (node >= N_NODES) return;
    int l = threadIdx.x & 31;
    int s = g_off[node], e = g_off[node + 1];

    float2 acc = make_float2(0.f, 0.f);
    int i = s;
    for (; i + 1 < e; i += 2) {
        uint2 p0 = __ldg(&g_perm[i]);
        uint2 p1 = __ldg(&g_perm[i + 1]);
        unsigned ua = __ldg(&g_y[(size_t)p0.x * 32 + l]);
        unsigned ub = __ldg(&g_y[(size_t)p1.x * 32 + l]);
        float2 va = __half22float2(*(__half2*)&ua);
        float2 vb = __half22float2(*(__half2*)&ub);
        float s0 = __uint_as_float(p0.y), s1 = __uint_as_float(p1.y);
        acc.x += va.x * s0 + vb.x * s1;
        acc.y += va.y * s0 + vb.y * s1;
    }
    if (i < e) {
        uint2 p = __ldg(&g_perm[i]);
        unsigned u = __ldg(&g_y[(size_t)p.x * 32 + l]);
        float2 v = __half22float2(*(__half2*)&u);
        float sc = __uint_as_float(p.y);
        acc.x += v.x * sc;
        acc.y += v.y * sc;
    }

    float2 o = out2[(size_t)node * 32 + l];  // self-loop + bias from GEMM
    o.x = fmaxf(o.x + acc.x, 0.f);
    o.y = fmaxf(o.y + acc.y, 0.f);
    out2[(size_t)node * 32 + l] = o;
}

// ---------------- launch ----------------
extern "C" void kernel_launch(void* const* d_in, const int* in_sizes, int n_in,
                              void* d_out, int out_size) {
    const float* x_author = (const float*)d_in[0];
    const float* x_field  = (const float*)d_in[1];
    const float* x_inst   = (const float*)d_in[2];
    const float* x_paper  = (const float*)d_in[3];
    const float* weight   = (const float*)d_in[4];
    const float* selfw    = (const float*)d_in[5];
    const float* bias     = (const float*)d_in[6];

    EdgeSet es;
    int total = 0;
    for (int r = 0; r < 7; r++) {
        es.src[r] = (const int*)d_in[7 + 2 * r];
        es.dst[r] = (const int*)d_in[8 + 2 * r];
        es.pre[r] = total;
        total += in_sizes[7 + 2 * r];
    }
    es.pre[7] = total;

    float* out = (float*)d_out;
    unsigned* yb; float* wb;
    cudaGetSymbolAddress((void**)&yb, g_y);
    cudaGetSymbolAddress((void**)&wb, g_w);

    float* out_author = out;
    float* out_field  = out + (size_t)N_AUTHOR * 64;
    float* out_inst   = out + (size_t)(N_AUTHOR + N_FIELD) * 64;
    float* out_paper  = out + (size_t)(N_AUTHOR + N_FIELD + N_INST) * 64;

    // weights + degree counting + CSR build (fused passes)
    pack_w_kernel<<<ceil_div(90112, 256), 256>>>(weight, selfw);
    zero_kernel<<<ceil_div(858000, 256), 256>>>();
    count_deg_kernel<<<ceil_div(total, 256), 256>>>(es);
    cdeg_kernel<<<ceil_div(N_NODES, 256), 256>>>();
    inv_deg_kernel<<<ceil_div(858000, 256), 256>>>();
    const int nchunks = ceil_div(N_NODES, 1024);  // 350
    scan1_kernel<<<nchunks, 256>>>();
    scan2_kernel<<<1, 512>>>(nchunks);
    scan3_kernel<<<nchunks, 1024>>>();
    place_kernel<<<ceil_div(total, 256), 256>>>(es);

    // fused projections per src type (self-loop block -> d_out with bias)
    {   // author: [W0 | W5 | self]
        OutPtrs o; o.p[0] = yb; o.p[1] = yb + (size_t)750000 * 32; o.p[2] = out_author; o.p[3] = nullptr;
        dim3 grid(ceil_div(N_AUTHOR, 128), 3);
        gemm_kernel<<<grid, 256>>>(x_author, wb + 0 * 8192, o, 2, bias, N_AUTHOR);
    }
    {   // paper: [W1 | W2 | W3 | self]
        OutPtrs o; o.p[0] = yb + (size_t)100000 * 32; o.p[1] = yb + (size_t)300000 * 32;
        o.p[2] = yb + (size_t)500000 * 32; o.p[3] = out_paper;
        dim3 grid(ceil_div(N_PAPER, 128), 4);
        gemm_kernel<<<grid, 256>>>(x_paper, wb + 3 * 8192, o, 3, bias, N_PAPER);
    }
    {   // field: [W4 | self]
        OutPtrs o; o.p[0] = yb + (size_t)700000 * 32; o.p[1] = out_field; o.p[2] = nullptr; o.p[3] = nullptr;
        dim3 grid(ceil_div(N_FIELD, 128), 2);
        gemm_kernel<<<grid, 256>>>(x_field, wb + 7 * 8192, o, 1, bias, N_FIELD);
    }
    {   // inst: [W6 | self]
        OutPtrs o; o.p[0] = yb + (size_t)850000 * 32; o.p[1] = out_inst; o.p[2] = nullptr; o.p[3] = nullptr;
        dim3 grid(ceil_div(N_INST, 128), 2);
        gemm_kernel<<<grid, 256>>>(x_inst, wb + 9 * 8192, o, 1, bias, N_INST);
    }

    // CSR gather-sum + fused ReLU
    accum_kernel<<<ceil_div(N_NODES, 8), 256>>>((float2*)out);
}

// round 5
// speedup vs baseline: 1.9970x; 1.1822x over previous
#include <cuda_runtime.h>
#include <cuda_fp16.h>
#include <cstdint>

#define N_AUTHOR 100000
#define N_PAPER  200000
#define N_FIELD  50000
#define N_INST   8000
// combined node space (== output row order): author[0,1e5) field[1e5,1.5e5) inst[1.5e5,1.58e5) paper[1.58e5,3.58e5)
#define N_NODES  358000
#define EDGE_CAP 5100000

// ---------------- static device scratch ----------------
__device__ unsigned g_y[27456000];       // fp16 messages: 858000 rows x 64 halves (32 uints/row)
__device__ unsigned g_deg[858000];       // per-rel dst degree -> invdeg float bits (in place)
__device__ int      g_off[N_NODES + 1];  // CSR offsets
__device__ int      g_cur[N_NODES];      // placement cursors
__device__ int      g_part[512];         // scan partials
__device__ uint2    g_perm[EDGE_CAP];    // per-edge payload: (y_row, invdeg bits)
__device__ float    g_w[90112];          // tf32 weights, 11 blocks of [128x64] row-major

__constant__ int c_DEG_OFF[7]   = {0, 200000, 300000, 500000, 550000, 750000, 758000};
__constant__ int c_Y_ROW[7]     = {0, 100000, 300000, 500000, 700000, 750000, 850000};
__constant__ int c_TYPE_BASE[7] = {158000, 0, 158000, 100000, 158000, 150000, 0};

struct EdgeSet {
    const int* src[7];
    const int* dst[7];
    int pre[8];   // exclusive prefix of edge counts, pre[7] = total
};

static inline int ceil_div(int a, int b) { return (a + b - 1) / b; }

// ---------------- prep kernels ----------------
// 11 column blocks of 64: [W0 W5 self | W1 W2 W3 self | W4 self | W6 self]
__global__ __launch_bounds__(256) void pack_w_kernel(const float* __restrict__ w,
                                                     const float* __restrict__ sw) {
    int i = blockIdx.x * 256 + threadIdx.x;
    if (i >= 90112) return;
    const int BLK_SRC[11] = {0, 5, 7, 1, 2, 3, 7, 4, 7, 6, 7};
    int blk = i >> 13, r = i & 8191;
    int s = BLK_SRC[blk];
    float v = (s == 7) ? sw[r] : w[s * 8192 + r];
    unsigned t;
    asm("cvt.rna.tf32.f32 %0, %1;" : "=r"(t) : "f"(v));
    g_w[i] = __uint_as_float(t);
}

__global__ __launch_bounds__(256) void zero_kernel() {
    int i = blockIdx.x * 256 + threadIdx.x;
    if (i < 858000) g_deg[i] = 0u;
    if (i < N_NODES) g_cur[i] = 0;
}

// one fused pass over all 7 relations
__global__ __launch_bounds__(256) void count_deg_kernel(EdgeSet es) {
    int idx = blockIdx.x * 256 + threadIdx.x;
    if (idx >= es.pre[7]) return;
    int r = 0;
#pragma unroll
    for (int k = 1; k < 7; ++k) r += (idx >= es.pre[k]);
    int i = idx - es.pre[r];
    atomicAdd(&g_deg[c_DEG_OFF[r] + __ldg(&es.dst[r][i])], 1u);
}

// combined degree of node i from RAW per-relation counts (before inv_deg overwrites)
__device__ __forceinline__ int combined_deg(int i) {
    if (i < 100000)  return (int)(g_deg[200000 + i] + g_deg[758000 + i]);               // author
    if (i < 150000)  return (int)g_deg[500000 + (i - 100000)];                           // field
    if (i < 158000)  return (int)g_deg[750000 + (i - 150000)];                           // inst
    int d = i - 158000; return (int)(g_deg[d] + g_deg[300000 + d] + g_deg[550000 + d]);  // paper
}

__global__ __launch_bounds__(256) void inv_deg_kernel() {
    int i = blockIdx.x * 256 + threadIdx.x;
    if (i < 858000) {
        unsigned d = g_deg[i];
        g_deg[i] = __float_as_uint(1.0f / (float)(d > 0u ? d : 1u));
    }
}

// ---------------- prefix scan over combined degrees (chunk=1024) ----------------
__global__ __launch_bounds__(256) void scan1_kernel() {
    int b = blockIdx.x, t = threadIdx.x;
    int base = b * 1024, s = 0;
#pragma unroll
    for (int k = 0; k < 4; ++k) {
        int i = base + t * 4 + k;
        if (i < N_NODES) s += combined_deg(i);
    }
    __shared__ int sm[256];
    sm[t] = s; __syncthreads();
    for (int d = 128; d > 0; d >>= 1) { if (t < d) sm[t] += sm[t + d]; __syncthreads(); }
    if (t == 0) g_part[b] = sm[0];
}

__global__ __launch_bounds__(512) void scan2_kernel(int nparts) {
    __shared__ int sm[512];
    int t = threadIdx.x;
    int v = (t < nparts) ? g_part[t] : 0;
    sm[t] = v; __syncthreads();
    for (int d = 1; d < 512; d <<= 1) {
        int x = (t >= d) ? sm[t - d] : 0; __syncthreads();
        sm[t] += x; __syncthreads();
    }
    if (t < nparts) g_part[t] = sm[t] - v;  // exclusive
    if (t == 511) g_off[N_NODES] = sm[511]; // total
}

__global__ __launch_bounds__(1024) void scan3_kernel() {
    int b = blockIdx.x, t = threadIdx.x;
    int i = b * 1024 + t;
    int v = (i < N_NODES) ? combined_deg(i) : 0;
    __shared__ int sm[1024];
    sm[t] = v; __syncthreads();
    for (int d = 1; d < 1024; d <<= 1) {
        int x = (t >= d) ? sm[t - d] : 0; __syncthreads();
        sm[t] += x; __syncthreads();
    }
    if (i < N_NODES) g_off[i] = g_part[b] + sm[t] - v;
}

// ---------------- fused edge placement (after inv_deg: scale resolved here) ----------------
__global__ __launch_bounds__(256) void place_kernel(EdgeSet es) {
    int idx = blockIdx.x * 256 + threadIdx.x;
    if (idx >= es.pre[7]) return;
    int r = 0;
#pragma unroll
    for (int k = 1; k < 7; ++k) r += (idx >= es.pre[k]);
    int i = idx - es.pre[r];
    int d = __ldg(&es.dst[r][i]);
    int gg = c_TYPE_BASE[r] + d;
    int pos = g_off[gg] + atomicAdd(&g_cur[gg], 1);
    g_perm[pos] = make_uint2((unsigned)(c_Y_ROW[r] + __ldg(&es.src[r][i])),
                             g_deg[c_DEG_OFF[r] + d]);
}

// ---------------- single fused tf32 GEMM over all 4 src types ----------------
// CTA = 128 rows of one type; loops over that type's column blocks INSIDE the
// kernel so the A tile is DRAM-read once and L2-hit for the remaining blocks.
struct GemmCfg {
    const float* A[4];
    void*        outp[4][4];  // [type][cb]: unsigned* (fp16 y) or float* (f32 out)
    int          wblk[4];     // first weight block index in g_w
    int          nblk[4];
    int          selfcb[4];   // cb index that is the self-loop (f32 + bias)
    int          M[4];
    int          pre[5];      // CTA prefix per type
};

__global__ __launch_bounds__(256) void gemm_kernel(GemmCfg cfg, const float* __restrict__ bias) {
    __shared__ unsigned Bs[128 * 72];  // stride 72 words: conflict-free frag loads
    const int tid = threadIdx.x, warp = tid >> 5, lane = tid & 31;
    const int g = lane >> 2, tig = lane & 3;

    const int b = blockIdx.x;
    int t = 0;
#pragma unroll
    for (int k = 1; k < 4; ++k) t += (b >= cfg.pre[k]);
    const int row0 = (b - cfg.pre[t]) * 128;
    const float* A = cfg.A[t];
    const int M = cfg.M[t];
    const int nblk = cfg.nblk[t];
    const int selfcb = cfg.selfcb[t];
    const float* wbase = g_w + (size_t)cfg.wblk[t] * 8192;

    const int r0g = row0 + warp * 16 + g;
    const bool v0 = r0g < M, v1 = (r0g + 8) < M;
    const float* A0 = A + (size_t)r0g * 128;
    const float* A1 = A0 + 8 * 128;

    for (int cb = 0; cb < nblk; ++cb) {
        // stage this column block's [128x64] tf32 weights
        __syncthreads();  // previous iteration's Bs reads complete
        const float4* bsrc = (const float4*)(wbase + (size_t)cb * 8192);
#pragma unroll
        for (int it = 0; it < 8; ++it) {
            int idx = it * 256 + tid;        // 0..2047 float4s
            int k = idx >> 4, j4 = idx & 15;
            float4 v = __ldg(bsrc + idx);
            *(float4*)&Bs[k * 72 + j4 * 4] = v;
        }
        __syncthreads();

        float c[8][4];
#pragma unroll
        for (int nb = 0; nb < 8; nb++)
#pragma unroll
            for (int j = 0; j < 4; j++) c[nb][j] = 0.f;

#pragma unroll
        for (int kc = 0; kc < 16; ++kc) {
            const int k0 = kc * 8;
            float f0 = v0 ? __ldg(A0 + k0 + tig)     : 0.f;
            float f2 = v0 ? __ldg(A0 + k0 + tig + 4) : 0.f;
            float f1 = v1 ? __ldg(A1 + k0 + tig)     : 0.f;
            float f3 = v1 ? __ldg(A1 + k0 + tig + 4) : 0.f;
            unsigned a0, a1, a2, a3;
            asm("cvt.rna.tf32.f32 %0, %1;" : "=r"(a0) : "f"(f0));
            asm("cvt.rna.tf32.f32 %0, %1;" : "=r"(a1) : "f"(f1));
            asm("cvt.rna.tf32.f32 %0, %1;" : "=r"(a2) : "f"(f2));
            asm("cvt.rna.tf32.f32 %0, %1;" : "=r"(a3) : "f"(f3));

            unsigned b0[8], b1[8];
#pragma unroll
            for (int nb = 0; nb < 8; ++nb) {
                b0[nb] = Bs[(k0 + tig) * 72 + nb * 8 + g];
                b1[nb] = Bs[(k0 + tig + 4) * 72 + nb * 8 + g];
            }
#pragma unroll
            for (int nb = 0; nb < 8; ++nb) {
                asm volatile(
                    "mma.sync.aligned.m16n8k8.row.col.f32.tf32.tf32.f32 "
                    "{%0,%1,%2,%3}, {%4,%5,%6,%7}, {%8,%9}, {%0,%1,%2,%3};"
                    : "+f"(c[nb][0]), "+f"(c[nb][1]), "+f"(c[nb][2]), "+f"(c[nb][3])
                    : "r"(a0), "r"(a1), "r"(a2), "r"(a3), "r"(b0[nb]), "r"(b1[nb]));
            }
        }

        if (cb == selfcb) {
            float* C = (float*)cfg.outp[t][cb];
#pragma unroll
            for (int nb = 0; nb < 8; ++nb) {
                int col = nb * 8 + tig * 2;
                float b0v = __ldg(&bias[col]), b1v = __ldg(&bias[col + 1]);
                if (v0) *(float2*)&C[(size_t)r0g * 64 + col] =
                            make_float2(c[nb][0] + b0v, c[nb][1] + b1v);
                if (v1) *(float2*)&C[(size_t)(r0g + 8) * 64 + col] =
                            make_float2(c[nb][2] + b0v, c[nb][3] + b1v);
            }
        } else {
            unsigned* C = (unsigned*)cfg.outp[t][cb];
#pragma unroll
            for (int nb = 0; nb < 8; ++nb) {
                int u = nb * 4 + tig;  // uint column index (2 halves)
                if (v0) {
                    __half2 h = __float22half2_rn(make_float2(c[nb][0], c[nb][1]));
                    C[(size_t)r0g * 32 + u] = *(unsigned*)&h;
                }
                if (v1) {
                    __half2 h = __float22half2_rn(make_float2(c[nb][2], c[nb][3]));
                    C[(size_t)(r0g + 8) * 32 + u] = *(unsigned*)&h;
                }
            }
        }
    }
}

// ---------------- CSR accumulate + ReLU: warp per node, half2 per lane ----------------
__global__ __launch_bounds__(256) void accum_kernel(float2* __restrict__ out2) {
    int node = blockIdx.x * 8 + (threadIdx.x >> 5);
    if (node >= N_NODES) return;
    int l = threadIdx.x & 31;
    int s = g_off[node], e = g_off[node + 1];

    float2 acc = make_float2(0.f, 0.f);
    int i = s;
    for (; i + 3 < e; i += 4) {
        uint2 p0 = __ldg(&g_perm[i]);
        uint2 p1 = __ldg(&g_perm[i + 1]);
        uint2 p2 = __ldg(&g_perm[i + 2]);
        uint2 p3 = __ldg(&g_perm[i + 3]);
        unsigned u0 = __ldg(&g_y[(size_t)p0.x * 32 + l]);
        unsigned u1 = __ldg(&g_y[(size_t)p1.x * 32 + l]);
        unsigned u2 = __ldg(&g_y[(size_t)p2.x * 32 + l]);
        unsigned u3 = __ldg(&g_y[(size_t)p3.x * 32 + l]);
        float2 v0 = __half22float2(*(__half2*)&u0);
        float2 v1 = __half22float2(*(__half2*)&u1);
        float2 v2 = __half22float2(*(__half2*)&u2);
        float2 v3 = __half22float2(*(__half2*)&u3);
        float s0 = __uint_as_float(p0.y), s1 = __uint_as_float(p1.y);
        float s2 = __uint_as_float(p2.y), s3 = __uint_as_float(p3.y);
        acc.x += v0.x * s0 + v1.x * s1 + v2.x * s2 + v3.x * s3;
        acc.y += v0.y * s0 + v1.y * s1 + v2.y * s2 + v3.y * s3;
    }
    for (; i < e; ++i) {
        uint2 p = __ldg(&g_perm[i]);
        unsigned u = __ldg(&g_y[(size_t)p.x * 32 + l]);
        float2 v = __half22float2(*(__half2*)&u);
        float sc = __uint_as_float(p.y);
        acc.x += v.x * sc;
        acc.y += v.y * sc;
    }

    float2 o = out2[(size_t)node * 32 + l];  // self-loop + bias from GEMM
    o.x = fmaxf(o.x + acc.x, 0.f);
    o.y = fmaxf(o.y + acc.y, 0.f);
    out2[(size_t)node * 32 + l] = o;
}

// ---------------- launch ----------------
extern "C" void kernel_launch(void* const* d_in, const int* in_sizes, int n_in,
                              void* d_out, int out_size) {
    const float* x_author = (const float*)d_in[0];
    const float* x_field  = (const float*)d_in[1];
    const float* x_inst   = (const float*)d_in[2];
    const float* x_paper  = (const float*)d_in[3];
    const float* weight   = (const float*)d_in[4];
    const float* selfw    = (const float*)d_in[5];
    const float* bias     = (const float*)d_in[6];

    EdgeSet es;
    int total = 0;
    for (int r = 0; r < 7; r++) {
        es.src[r] = (const int*)d_in[7 + 2 * r];
        es.dst[r] = (const int*)d_in[8 + 2 * r];
        es.pre[r] = total;
        total += in_sizes[7 + 2 * r];
    }
    es.pre[7] = total;

    float* out = (float*)d_out;
    unsigned* yb;
    cudaGetSymbolAddress((void**)&yb, g_y);

    float* out_author = out;
    float* out_field  = out + (size_t)N_AUTHOR * 64;
    float* out_inst   = out + (size_t)(N_AUTHOR + N_FIELD) * 64;
    float* out_paper  = out + (size_t)(N_AUTHOR + N_FIELD + N_INST) * 64;

    // weights + degrees + CSR build
    pack_w_kernel<<<ceil_div(90112, 256), 256>>>(weight, selfw);
    zero_kernel<<<ceil_div(858000, 256), 256>>>();
    count_deg_kernel<<<ceil_div(total, 256), 256>>>(es);
    const int nchunks = ceil_div(N_NODES, 1024);  // 350
    scan1_kernel<<<nchunks, 256>>>();
    scan2_kernel<<<1, 512>>>(nchunks);
    scan3_kernel<<<nchunks, 1024>>>();
    inv_deg_kernel<<<ceil_div(858000, 256), 256>>>();
    place_kernel<<<ceil_div(total, 256), 256>>>(es);

    // single fused projection launch over all 4 src types
    GemmCfg cfg;
    cfg.A[0] = x_author; cfg.A[1] = x_paper; cfg.A[2] = x_field; cfg.A[3] = x_inst;
    cfg.M[0] = N_AUTHOR; cfg.M[1] = N_PAPER; cfg.M[2] = N_FIELD; cfg.M[3] = N_INST;
    cfg.wblk[0] = 0; cfg.wblk[1] = 3; cfg.wblk[2] = 7; cfg.wblk[3] = 9;
    cfg.nblk[0] = 3; cfg.nblk[1] = 4; cfg.nblk[2] = 2; cfg.nblk[3] = 2;
    cfg.selfcb[0] = 2; cfg.selfcb[1] = 3; cfg.selfcb[2] = 1; cfg.selfcb[3] = 1;
    // author: [W0 | W5 | self]
    cfg.outp[0][0] = yb;                         cfg.outp[0][1] = yb + (size_t)750000 * 32;
    cfg.outp[0][2] = out_author;                 cfg.outp[0][3] = nullptr;
    // paper: [W1 | W2 | W3 | self]
    cfg.outp[1][0] = yb + (size_t)100000 * 32;   cfg.outp[1][1] = yb + (size_t)300000 * 32;
    cfg.outp[1][2] = yb + (size_t)500000 * 32;   cfg.outp[1][3] = out_paper;
    // field: [W4 | self]
    cfg.outp[2][0] = yb + (size_t)700000 * 32;   cfg.outp[2][1] = out_field;
    cfg.outp[2][2] = nullptr;                    cfg.outp[2][3] = nullptr;
    // inst: [W6 | self]
    cfg.outp[3][0] = yb + (size_t)850000 * 32;   cfg.outp[3][1] = out_inst;
    cfg.outp[3][2] = nullptr;                    cfg.outp[3][3] = nullptr;
    cfg.pre[0] = 0;
    cfg.pre[1] = cfg.pre[0] + ceil_div(N_AUTHOR, 128);  // 782
    cfg.pre[2] = cfg.pre[1] + ceil_div(N_PAPER, 128);   // 2345
    cfg.pre[3] = cfg.pre[2] + ceil_div(N_FIELD, 128);   // 2736
    cfg.pre[4] = cfg.pre[3] + ceil_div(N_INST, 128);    // 2799
    gemm_kernel<<<cfg.pre[4], 256>>>(cfg, bias);

    // CSR gather-sum + fused ReLU
    accum_kernel<<<ceil_div(N_NODES, 8), 256>>>((float2*)out);
}

// round 6
// speedup vs baseline: 2.0361x; 1.0196x over previous
#include <cuda_runtime.h>
#include <cuda_fp16.h>
#include <cstdint>

#define N_AUTHOR 100000
#define N_PAPER  200000
#define N_FIELD  50000
#define N_INST   8000
// combined node space (== output row order): author[0,1e5) field[1e5,1.5e5) inst[1.5e5,1.58e5) paper[1.58e5,3.58e5)
#define N_NODES  358000
#define EDGE_CAP 5100000

// ---------------- static device scratch ----------------
__device__ unsigned g_y[27456000];       // fp16 messages: 858000 rows x 64 halves (32 uints/row)
__device__ unsigned g_deg[858000];       // per-rel dst degree -> invdeg float bits (in place)
__device__ int      g_off[N_NODES + 1];  // CSR offsets
__device__ int      g_cur[N_NODES];      // placement cursors
__device__ int      g_part[512];         // scan partials
__device__ unsigned g_perm[EDGE_CAP];    // per-edge payload: (rel<<20 | y_row)
__device__ float    g_w[90112];          // tf32 weights, 11 blocks of [128x64] row-major

__constant__ int c_DEG_OFF[7]    = {0, 200000, 300000, 500000, 550000, 750000, 758000};
__constant__ int c_Y_ROW[7]      = {0, 100000, 300000, 500000, 700000, 750000, 850000};
__constant__ int c_TYPE_BASE[7]  = {158000, 0, 158000, 100000, 158000, 150000, 0};
// SCALE_BASE[r] = DEG_OFF[r] - TYPE_BASE[r]  (invdeg index = SCALE_BASE[r] + combined_node)
__constant__ int c_SCALE_BASE[7] = {-158000, 200000, 142000, 400000, 392000, 600000, 758000};

struct EdgeSet {
    const int* src[7];
    const int* dst[7];
    int pre[8];   // exclusive prefix of edge counts, pre[7] = total
};

static inline int ceil_div(int a, int b) { return (a + b - 1) / b; }

// ---------------- prep kernels ----------------
// 11 column blocks of 64: [W0 W5 self | W1 W2 W3 self | W4 self | W6 self]
__global__ __launch_bounds__(256) void pack_w_kernel(const float* __restrict__ w,
                                                     const float* __restrict__ sw) {
    int i = blockIdx.x * 256 + threadIdx.x;
    if (i >= 90112) return;
    const int BLK_SRC[11] = {0, 5, 7, 1, 2, 3, 7, 4, 7, 6, 7};
    int blk = i >> 13, r = i & 8191;
    int s = BLK_SRC[blk];
    float v = (s == 7) ? sw[r] : w[s * 8192 + r];
    unsigned t;
    asm("cvt.rna.tf32.f32 %0, %1;" : "=r"(t) : "f"(v));
    g_w[i] = __uint_as_float(t);
}

__global__ __launch_bounds__(256) void zero_kernel() {
    int i = blockIdx.x * 256 + threadIdx.x;
    if (i < 858000) g_deg[i] = 0u;
    if (i < N_NODES) g_cur[i] = 0;
}

// one fused pass over all 7 relations
__global__ __launch_bounds__(256) void count_deg_kernel(EdgeSet es) {
    int idx = blockIdx.x * 256 + threadIdx.x;
    if (idx >= es.pre[7]) return;
    int r = 0;
#pragma unroll
    for (int k = 1; k < 7; ++k) r += (idx >= es.pre[k]);
    int i = idx - es.pre[r];
    atomicAdd(&g_deg[c_DEG_OFF[r] + __ldg(&es.dst[r][i])], 1u);
}

// combined degree of node i from RAW per-relation counts (before inv_deg overwrites)
__device__ __forceinline__ int combined_deg(int i) {
    if (i < 100000)  return (int)(g_deg[200000 + i] + g_deg[758000 + i]);               // author
    if (i < 150000)  return (int)g_deg[500000 + (i - 100000)];                           // field
    if (i < 158000)  return (int)g_deg[750000 + (i - 150000)];                           // inst
    int d = i - 158000; return (int)(g_deg[d] + g_deg[300000 + d] + g_deg[550000 + d]);  // paper
}

__global__ __launch_bounds__(256) void inv_deg_kernel() {
    int i = blockIdx.x * 256 + threadIdx.x;
    if (i < 858000) {
        unsigned d = g_deg[i];
        g_deg[i] = __float_as_uint(1.0f / (float)(d > 0u ? d : 1u));
    }
}

// ---------------- prefix scan over combined degrees (chunk=1024) ----------------
__global__ __launch_bounds__(256) void scan1_kernel() {
    int b = blockIdx.x, t = threadIdx.x;
    int base = b * 1024, s = 0;
#pragma unroll
    for (int k = 0; k < 4; ++k) {
        int i = base + t * 4 + k;
        if (i < N_NODES) s += combined_deg(i);
    }
    __shared__ int sm[256];
    sm[t] = s; __syncthreads();
    for (int d = 128; d > 0; d >>= 1) { if (t < d) sm[t] += sm[t + d]; __syncthreads(); }
    if (t == 0) g_part[b] = sm[0];
}

__global__ __launch_bounds__(512) void scan2_kernel(int nparts) {
    __shared__ int sm[512];
    int t = threadIdx.x;
    int v = (t < nparts) ? g_part[t] : 0;
    sm[t] = v; __syncthreads();
    for (int d = 1; d < 512; d <<= 1) {
        int x = (t >= d) ? sm[t - d] : 0; __syncthreads();
        sm[t] += x; __syncthreads();
    }
    if (t < nparts) g_part[t] = sm[t] - v;  // exclusive
    if (t == 511) g_off[N_NODES] = sm[511]; // total
}

__global__ __launch_bounds__(1024) void scan3_kernel() {
    int b = blockIdx.x, t = threadIdx.x;
    int i = b * 1024 + t;
    int v = (i < N_NODES) ? combined_deg(i) : 0;
    __shared__ int sm[1024];
    sm[t] = v; __syncthreads();
    for (int d = 1; d < 1024; d <<= 1) {
        int x = (t >= d) ? sm[t - d] : 0; __syncthreads();
        sm[t] += x; __syncthreads();
    }
    if (i < N_NODES) g_off[i] = g_part[b] + sm[t] - v;
}

// ---------------- fused edge placement (payload = rel<<20 | y_row) ----------------
__global__ __launch_bounds__(256) void place_kernel(EdgeSet es) {
    int idx = blockIdx.x * 256 + threadIdx.x;
    if (idx >= es.pre[7]) return;
    int r = 0;
#pragma unroll
    for (int k = 1; k < 7; ++k) r += (idx >= es.pre[k]);
    int i = idx - es.pre[r];
    int d = __ldg(&es.dst[r][i]);
    int gg = c_TYPE_BASE[r] + d;
    int pos = g_off[gg] + atomicAdd(&g_cur[gg], 1);
    g_perm[pos] = ((unsigned)r << 20) | (unsigned)(c_Y_ROW[r] + __ldg(&es.src[r][i]));
}

// ---------------- single fused tf32 GEMM over all 4 src types ----------------
// CTA = 128 rows of one type; loops over that type's column blocks INSIDE the
// kernel so the A tile is DRAM-read once and L1/L2-hit for remaining blocks.
struct GemmCfg {
    const float* A[4];
    void*        outp[4][4];  // [type][cb]: unsigned* (fp16 y) or float* (f32 out)
    int          wblk[4];     // first weight block index in g_w
    int          nblk[4];
    int          selfcb[4];   // cb index that is the self-loop (f32 + bias)
    int          M[4];
    int          pre[5];      // CTA prefix per type
};

__global__ __launch_bounds__(256) void gemm_kernel(GemmCfg cfg, const float* __restrict__ bias) {
    __shared__ unsigned Bs[128 * 72];  // stride 72 words: conflict-free frag loads
    const int tid = threadIdx.x, warp = tid >> 5, lane = tid & 31;
    const int g = lane >> 2, tig = lane & 3;

    const int b = blockIdx.x;
    int t = 0;
#pragma unroll
    for (int k = 1; k < 4; ++k) t += (b >= cfg.pre[k]);
    const int row0 = (b - cfg.pre[t]) * 128;
    const float* A = cfg.A[t];
    const int M = cfg.M[t];
    const int nblk = cfg.nblk[t];
    const int selfcb = cfg.selfcb[t];
    const float* wbase = g_w + (size_t)cfg.wblk[t] * 8192;

    const int r0g = row0 + warp * 16 + g;
    const bool v0 = r0g < M, v1 = (r0g + 8) < M;
    const float* A0 = A + (size_t)r0g * 128;
    const float* A1 = A0 + 8 * 128;

    for (int cb = 0; cb < nblk; ++cb) {
        __syncthreads();  // previous iteration's Bs reads complete
        const float4* bsrc = (const float4*)(wbase + (size_t)cb * 8192);
#pragma unroll
        for (int it = 0; it < 8; ++it) {
            int idx = it * 256 + tid;        // 0..2047 float4s
            int k = idx >> 4, j4 = idx & 15;
            float4 v = __ldg(bsrc + idx);
            *(float4*)&Bs[k * 72 + j4 * 4] = v;
        }
        __syncthreads();

        float c[8][4];
#pragma unroll
        for (int nb = 0; nb < 8; nb++)
#pragma unroll
            for (int j = 0; j < 4; j++) c[nb][j] = 0.f;

#pragma unroll
        for (int kc = 0; kc < 16; ++kc) {
            const int k0 = kc * 8;
            float f0 = v0 ? __ldg(A0 + k0 + tig)     : 0.f;
            float f2 = v0 ? __ldg(A0 + k0 + tig + 4) : 0.f;
            float f1 = v1 ? __ldg(A1 + k0 + tig)     : 0.f;
            float f3 = v1 ? __ldg(A1 + k0 + tig + 4) : 0.f;
            unsigned a0, a1, a2, a3;
            asm("cvt.rna.tf32.f32 %0, %1;" : "=r"(a0) : "f"(f0));
            asm("cvt.rna.tf32.f32 %0, %1;" : "=r"(a1) : "f"(f1));
            asm("cvt.rna.tf32.f32 %0, %1;" : "=r"(a2) : "f"(f2));
            asm("cvt.rna.tf32.f32 %0, %1;" : "=r"(a3) : "f"(f3));

            unsigned b0[8], b1[8];
#pragma unroll
            for (int nb = 0; nb < 8; ++nb) {
                b0[nb] = Bs[(k0 + tig) * 72 + nb * 8 + g];
                b1[nb] = Bs[(k0 + tig + 4) * 72 + nb * 8 + g];
            }
#pragma unroll
            for (int nb = 0; nb < 8; ++nb) {
                asm volatile(
                    "mma.sync.aligned.m16n8k8.row.col.f32.tf32.tf32.f32 "
                    "{%0,%1,%2,%3}, {%4,%5,%6,%7}, {%8,%9}, {%0,%1,%2,%3};"
                    : "+f"(c[nb][0]), "+f"(c[nb][1]), "+f"(c[nb][2]), "+f"(c[nb][3])
                    : "r"(a0), "r"(a1), "r"(a2), "r"(a3), "r"(b0[nb]), "r"(b1[nb]));
            }
        }

        if (cb == selfcb) {
            float* C = (float*)cfg.outp[t][cb];
#pragma unroll
            for (int nb = 0; nb < 8; ++nb) {
                int col = nb * 8 + tig * 2;
                float b0v = __ldg(&bias[col]), b1v = __ldg(&bias[col + 1]);
                if (v0) *(float2*)&C[(size_t)r0g * 64 + col] =
                            make_float2(c[nb][0] + b0v, c[nb][1] + b1v);
                if (v1) *(float2*)&C[(size_t)(r0g + 8) * 64 + col] =
                            make_float2(c[nb][2] + b0v, c[nb][3] + b1v);
            }
        } else {
            unsigned* C = (unsigned*)cfg.outp[t][cb];
#pragma unroll
            for (int nb = 0; nb < 8; ++nb) {
                int u = nb * 4 + tig;  // uint column index (2 halves)
                if (v0) {
                    __half2 h = __float22half2_rn(make_float2(c[nb][0], c[nb][1]));
                    C[(size_t)r0g * 32 + u] = *(unsigned*)&h;
                }
                if (v1) {
                    __half2 h = __float22half2_rn(make_float2(c[nb][2], c[nb][3]));
                    C[(size_t)(r0g + 8) * 32 + u] = *(unsigned*)&h;
                }
            }
        }
    }
}

// ---------------- CSR accumulate + ReLU: warp per node, half2 per lane ----------------
__global__ __launch_bounds__(256) void accum_kernel(float2* __restrict__ out2) {
    int node = blockIdx.x * 8 + (threadIdx.x >> 5);
    if (node >= N_NODES) return;
    int l = threadIdx.x & 31;
    int s = g_off[node], e = g_off[node + 1];

    float2 acc = make_float2(0.f, 0.f);
    int i = s;
    for (; i + 3 < e; i += 4) {
        unsigned p0 = __ldg(&g_perm[i]);
        unsigned p1 = __ldg(&g_perm[i + 1]);
        unsigned p2 = __ldg(&g_perm[i + 2]);
        unsigned p3 = __ldg(&g_perm[i + 3]);
        unsigned u0 = __ldg(&g_y[(size_t)(p0 & 0xFFFFFu) * 32 + l]);
        unsigned u1 = __ldg(&g_y[(size_t)(p1 & 0xFFFFFu) * 32 + l]);
        unsigned u2 = __ldg(&g_y[(size_t)(p2 & 0xFFFFFu) * 32 + l]);
        unsigned u3 = __ldg(&g_y[(size_t)(p3 & 0xFFFFFu) * 32 + l]);
        float s0 = __uint_as_float(g_deg[c_SCALE_BASE[p0 >> 20] + node]);
        float s1 = __uint_as_float(g_deg[c_SCALE_BASE[p1 >> 20] + node]);
        float s2 = __uint_as_float(g_deg[c_SCALE_BASE[p2 >> 20] + node]);
        float s3 = __uint_as_float(g_deg[c_SCALE_BASE[p3 >> 20] + node]);
        float2 v0 = __half22float2(*(__half2*)&u0);
        float2 v1 = __half22float2(*(__half2*)&u1);
        float2 v2 = __half22float2(*(__half2*)&u2);
        float2 v3 = __half22float2(*(__half2*)&u3);
        acc.x += v0.x * s0 + v1.x * s1 + v2.x * s2 + v3.x * s3;
        acc.y += v0.y * s0 + v1.y * s1 + v2.y * s2 + v3.y * s3;
    }
    for (; i < e; ++i) {
        unsigned p = __ldg(&g_perm[i]);
        unsigned u = __ldg(&g_y[(size_t)(p & 0xFFFFFu) * 32 + l]);
        float sc = __uint_as_float(g_deg[c_SCALE_BASE[p >> 20] + node]);
        float2 v = __half22float2(*(__half2*)&u);
        acc.x += v.x * sc;
        acc.y += v.y * sc;
    }

    float2 o = out2[(size_t)node * 32 + l];  // self-loop + bias from GEMM
    o.x = fmaxf(o.x + acc.x, 0.f);
    o.y = fmaxf(o.y + acc.y, 0.f);
    out2[(size_t)node * 32 + l] = o;
}

// ---------------- launch ----------------
static cudaStream_t g_s2;
static cudaEvent_t  g_fork, g_join;
static bool         g_streams_ready = false;

extern "C" void kernel_launch(void* const* d_in, const int* in_sizes, int n_in,
                              void* d_out, int out_size) {
    const float* x_author = (const float*)d_in[0];
    const float* x_field  = (const float*)d_in[1];
    const float* x_inst   = (const float*)d_in[2];
    const float* x_paper  = (const float*)d_in[3];
    const float* weight   = (const float*)d_in[4];
    const float* selfw    = (const float*)d_in[5];
    const float* bias     = (const float*)d_in[6];

    EdgeSet es;
    int total = 0;
    for (int r = 0; r < 7; r++) {
        es.src[r] = (const int*)d_in[7 + 2 * r];
        es.dst[r] = (const int*)d_in[8 + 2 * r];
        es.pre[r] = total;
        total += in_sizes[7 + 2 * r];
    }
    es.pre[7] = total;

    float* out = (float*)d_out;
    unsigned* yb;
    cudaGetSymbolAddress((void**)&yb, g_y);

    float* out_author = out;
    float* out_field  = out + (size_t)N_AUTHOR * 64;
    float* out_inst   = out + (size_t)(N_AUTHOR + N_FIELD) * 64;
    float* out_paper  = out + (size_t)(N_AUTHOR + N_FIELD + N_INST) * 64;

    if (!g_streams_ready) {  // first call is uncaptured; handles reused at capture
        cudaStreamCreateWithFlags(&g_s2, cudaStreamNonBlocking);
        cudaEventCreateWithFlags(&g_fork, cudaEventDisableTiming);
        cudaEventCreateWithFlags(&g_join, cudaEventDisableTiming);
        g_streams_ready = true;
    }

    // ---- fork: side stream = weights + GEMM (independent of edge lists) ----
    cudaEventRecord(g_fork, 0);
    cudaStreamWaitEvent(g_s2, g_fork, 0);

    pack_w_kernel<<<ceil_div(90112, 256), 256, 0, g_s2>>>(weight, selfw);

    GemmCfg cfg;
    cfg.A[0] = x_author; cfg.A[1] = x_paper; cfg.A[2] = x_field; cfg.A[3] = x_inst;
    cfg.M[0] = N_AUTHOR; cfg.M[1] = N_PAPER; cfg.M[2] = N_FIELD; cfg.M[3] = N_INST;
    cfg.wblk[0] = 0; cfg.wblk[1] = 3; cfg.wblk[2] = 7; cfg.wblk[3] = 9;
    cfg.nblk[0] = 3; cfg.nblk[1] = 4; cfg.nblk[2] = 2; cfg.nblk[3] = 2;
    cfg.selfcb[0] = 2; cfg.selfcb[1] = 3; cfg.selfcb[2] = 1; cfg.selfcb[3] = 1;
    cfg.outp[0][0] = yb;                         cfg.outp[0][1] = yb + (size_t)750000 * 32;
    cfg.outp[0][2] = out_author;                 cfg.outp[0][3] = nullptr;
    cfg.outp[1][0] = yb + (size_t)100000 * 32;   cfg.outp[1][1] = yb + (size_t)300000 * 32;
    cfg.outp[1][2] = yb + (size_t)500000 * 32;   cfg.outp[1][3] = out_paper;
    cfg.outp[2][0] = yb + (size_t)700000 * 32;   cfg.outp[2][1] = out_field;
    cfg.outp[2][2] = nullptr;                    cfg.outp[2][3] = nullptr;
    cfg.outp[3][0] = yb + (size_t)850000 * 32;   cfg.outp[3][1] = out_inst;
    cfg.outp[3][2] = nullptr;                    cfg.outp[3][3] = nullptr;
    cfg.pre[0] = 0;
    cfg.pre[1] = cfg.pre[0] + ceil_div(N_AUTHOR, 128);  // 782
    cfg.pre[2] = cfg.pre[1] + ceil_div(N_PAPER, 128);   // 2345
    cfg.pre[3] = cfg.pre[2] + ceil_div(N_FIELD, 128);   // 2736
    cfg.pre[4] = cfg.pre[3] + ceil_div(N_INST, 128);    // 2799
    gemm_kernel<<<cfg.pre[4], 256, 0, g_s2>>>(cfg, bias);
    cudaEventRecord(g_join, g_s2);

    // ---- main stream: CSR build (independent of features/weights) ----
    zero_kernel<<<ceil_div(858000, 256), 256>>>();
    count_deg_kernel<<<ceil_div(total, 256), 256>>>(es);
    const int nchunks = ceil_div(N_NODES, 1024);  // 350
    scan1_kernel<<<nchunks, 256>>>();
    scan2_kernel<<<1, 512>>>(nchunks);
    scan3_kernel<<<nchunks, 1024>>>();
    place_kernel<<<ceil_div(total, 256), 256>>>(es);
    inv_deg_kernel<<<ceil_div(858000, 256), 256>>>();

    // ---- join, then gather-sum + fused ReLU ----
    cudaStreamWaitEvent(0, g_join, 0);
    accum_kernel<<<ceil_div(N_NODES, 8), 256>>>((float2*)out);
}

// round 7
// speedup vs baseline: 2.1338x; 1.0480x over previous
#include <cuda_runtime.h>
#include <cuda_fp16.h>
#include <cstdint>

#define N_AUTHOR 100000
#define N_PAPER  200000
#define N_FIELD  50000
#define N_INST   8000
// combined node space (== output row order): author[0,1e5) field[1e5,1.5e5) inst[1.5e5,1.58e5) paper[1.58e5,3.58e5)
#define N_NODES  358000
#define EDGE_CAP 5100000

// ---------------- static device scratch ----------------
__device__ unsigned g_y[27456000];       // fp16 messages: 858000 rows x 64 halves (32 uints/row)
__device__ unsigned g_deg[858000];       // per-rel dst degree -> invdeg float bits (in place)
__device__ int      g_off[N_NODES + 1];  // CSR offsets
__device__ int      g_cur[N_NODES];      // placement cursors
__device__ int      g_part[512];         // scan partials
__device__ unsigned g_perm[EDGE_CAP];    // per-edge payload: (rel<<20 | y_row)
__device__ float    g_w[90112];          // tf32 weights, 11 blocks of [128x64] row-major

__constant__ int c_DEG_OFF[7]    = {0, 200000, 300000, 500000, 550000, 750000, 758000};
__constant__ int c_Y_ROW[7]      = {0, 100000, 300000, 500000, 700000, 750000, 850000};
__constant__ int c_TYPE_BASE[7]  = {158000, 0, 158000, 100000, 158000, 150000, 0};
// SCALE_BASE[r] = DEG_OFF[r] - TYPE_BASE[r]  (invdeg index = SCALE_BASE[r] + combined_node)
__constant__ int c_SCALE_BASE[7] = {-158000, 200000, 142000, 400000, 392000, 600000, 758000};

struct EdgeSet {
    const int* src[7];
    const int* dst[7];
    int pre[8];   // exclusive prefix of edge counts, pre[7] = total
};

static inline int ceil_div(int a, int b) { return (a + b - 1) / b; }

// ---------------- prep kernels ----------------
// 11 column blocks of 64: [W0 W5 self | W1 W2 W3 self | W4 self | W6 self]
__global__ __launch_bounds__(256) void pack_w_kernel(const float* __restrict__ w,
                                                     const float* __restrict__ sw) {
    int i = blockIdx.x * 256 + threadIdx.x;
    if (i >= 90112) return;
    const int BLK_SRC[11] = {0, 5, 7, 1, 2, 3, 7, 4, 7, 6, 7};
    int blk = i >> 13, r = i & 8191;
    int s = BLK_SRC[blk];
    float v = (s == 7) ? sw[r] : w[s * 8192 + r];
    unsigned t;
    asm("cvt.rna.tf32.f32 %0, %1;" : "=r"(t) : "f"(v));
    g_w[i] = __uint_as_float(t);
}

__global__ __launch_bounds__(256) void zero_kernel() {
    int i = blockIdx.x * 256 + threadIdx.x;
    if (i < 858000) g_deg[i] = 0u;
    if (i < N_NODES) g_cur[i] = 0;
}

// one fused pass over all 7 relations
__global__ __launch_bounds__(256) void count_deg_kernel(EdgeSet es) {
    int idx = blockIdx.x * 256 + threadIdx.x;
    if (idx >= es.pre[7]) return;
    int r = 0;
#pragma unroll
    for (int k = 1; k < 7; ++k) r += (idx >= es.pre[k]);
    int i = idx - es.pre[r];
    atomicAdd(&g_deg[c_DEG_OFF[r] + __ldcs(&es.dst[r][i])], 1u);
}

// combined degree of node i from RAW per-relation counts (before inv_deg overwrites)
__device__ __forceinline__ int combined_deg(int i) {
    if (i < 100000)  return (int)(g_deg[200000 + i] + g_deg[758000 + i]);               // author
    if (i < 150000)  return (int)g_deg[500000 + (i - 100000)];                           // field
    if (i < 158000)  return (int)g_deg[750000 + (i - 150000)];                           // inst
    int d = i - 158000; return (int)(g_deg[d] + g_deg[300000 + d] + g_deg[550000 + d]);  // paper
}

__global__ __launch_bounds__(256) void inv_deg_kernel() {
    int i = blockIdx.x * 256 + threadIdx.x;
    if (i < 858000) {
        unsigned d = g_deg[i];
        g_deg[i] = __float_as_uint(1.0f / (float)(d > 0u ? d : 1u));
    }
}

// ---------------- prefix scan over combined degrees (chunk=1024) ----------------
__global__ __launch_bounds__(256) void scan1_kernel() {
    int b = blockIdx.x, t = threadIdx.x;
    int base = b * 1024, s = 0;
#pragma unroll
    for (int k = 0; k < 4; ++k) {
        int i = base + t * 4 + k;
        if (i < N_NODES) s += combined_deg(i);
    }
    __shared__ int sm[256];
    sm[t] = s; __syncthreads();
    for (int d = 128; d > 0; d >>= 1) { if (t < d) sm[t] += sm[t + d]; __syncthreads(); }
    if (t == 0) g_part[b] = sm[0];
}

__global__ __launch_bounds__(512) void scan2_kernel(int nparts) {
    __shared__ int sm[512];
    int t = threadIdx.x;
    int v = (t < nparts) ? g_part[t] : 0;
    sm[t] = v; __syncthreads();
    for (int d = 1; d < 512; d <<= 1) {
        int x = (t >= d) ? sm[t - d] : 0; __syncthreads();
        sm[t] += x; __syncthreads();
    }
    if (t < nparts) g_part[t] = sm[t] - v;  // exclusive
    if (t == 511) g_off[N_NODES] = sm[511]; // total
}

__global__ __launch_bounds__(1024) void scan3_kernel() {
    int b = blockIdx.x, t = threadIdx.x;
    int i = b * 1024 + t;
    int v = (i < N_NODES) ? combined_deg(i) : 0;
    __shared__ int sm[1024];
    sm[t] = v; __syncthreads();
    for (int d = 1; d < 1024; d <<= 1) {
        int x = (t >= d) ? sm[t - d] : 0; __syncthreads();
        sm[t] += x; __syncthreads();
    }
    if (i < N_NODES) g_off[i] = g_part[b] + sm[t] - v;
}

// ---------------- fused edge placement (payload = rel<<20 | y_row) ----------------
__global__ __launch_bounds__(256) void place_kernel(EdgeSet es) {
    int idx = blockIdx.x * 256 + threadIdx.x;
    if (idx >= es.pre[7]) return;
    int r = 0;
#pragma unroll
    for (int k = 1; k < 7; ++k) r += (idx >= es.pre[k]);
    int i = idx - es.pre[r];
    int d = __ldcs(&es.dst[r][i]);
    int gg = c_TYPE_BASE[r] + d;
    int pos = g_off[gg] + atomicAdd(&g_cur[gg], 1);
    __stcs(&g_perm[pos], ((unsigned)r << 20) | (unsigned)(c_Y_ROW[r] + __ldcs(&es.src[r][i])));
}

// ---------------- single fused tf32 GEMM over all 4 src types ----------------
// CTA = 128 rows of one type. A fragments are loaded + tf32-converted ONCE into
// registers (64 regs/thread) and reused across that type's column blocks.
struct GemmCfg {
    const float* A[4];
    void*        outp[4][4];  // [type][cb]: unsigned* (fp16 y) or float* (f32 out)
    int          wblk[4];     // first weight block index in g_w
    int          nblk[4];
    int          selfcb[4];   // cb index that is the self-loop (f32 + bias)
    int          M[4];
    int          pre[5];      // CTA prefix per type
};

__global__ __launch_bounds__(256, 2) void gemm_kernel(GemmCfg cfg, const float* __restrict__ bias) {
    __shared__ unsigned Bs[128 * 72];  // stride 72 words: conflict-free frag loads
    const int tid = threadIdx.x, warp = tid >> 5, lane = tid & 31;
    const int g = lane >> 2, tig = lane & 3;

    const int b = blockIdx.x;
    int t = 0;
#pragma unroll
    for (int k = 1; k < 4; ++k) t += (b >= cfg.pre[k]);
    const int row0 = (b - cfg.pre[t]) * 128;
    const int M = cfg.M[t];
    const int nblk = cfg.nblk[t];
    const int selfcb = cfg.selfcb[t];
    const float* wbase = g_w + (size_t)cfg.wblk[t] * 8192;

    const int r0g = row0 + warp * 16 + g;
    const bool v0 = r0g < M, v1 = (r0g + 8) < M;
    const float* A0 = cfg.A[t] + (size_t)r0g * 128;
    const float* A1 = A0 + 8 * 128;

    // A fragments: load + convert once, reuse for every column block
    unsigned ar0[16], ar1[16], ar2[16], ar3[16];
#pragma unroll
    for (int kc = 0; kc < 16; ++kc) {
        const int k0 = kc * 8;
        float f0 = v0 ? __ldg(A0 + k0 + tig)     : 0.f;
        float f2 = v0 ? __ldg(A0 + k0 + tig + 4) : 0.f;
        float f1 = v1 ? __ldg(A1 + k0 + tig)     : 0.f;
        float f3 = v1 ? __ldg(A1 + k0 + tig + 4) : 0.f;
        asm("cvt.rna.tf32.f32 %0, %1;" : "=r"(ar0[kc]) : "f"(f0));
        asm("cvt.rna.tf32.f32 %0, %1;" : "=r"(ar1[kc]) : "f"(f1));
        asm("cvt.rna.tf32.f32 %0, %1;" : "=r"(ar2[kc]) : "f"(f2));
        asm("cvt.rna.tf32.f32 %0, %1;" : "=r"(ar3[kc]) : "f"(f3));
    }

    for (int cb = 0; cb < nblk; ++cb) {
        __syncthreads();  // previous iteration's Bs reads complete
        const float4* bsrc = (const float4*)(wbase + (size_t)cb * 8192);
#pragma unroll
        for (int it = 0; it < 8; ++it) {
            int idx = it * 256 + tid;        // 0..2047 float4s
            int k = idx >> 4, j4 = idx & 15;
            float4 v = __ldg(bsrc + idx);
            *(float4*)&Bs[k * 72 + j4 * 4] = v;
        }
        __syncthreads();

        float c[8][4];
#pragma unroll
        for (int nb = 0; nb < 8; nb++)
#pragma unroll
            for (int j = 0; j < 4; j++) c[nb][j] = 0.f;

#pragma unroll
        for (int kc = 0; kc < 16; ++kc) {
            const int k0 = kc * 8;
            unsigned b0[8], b1[8];
#pragma unroll
            for (int nb = 0; nb < 8; ++nb) {
                b0[nb] = Bs[(k0 + tig) * 72 + nb * 8 + g];
                b1[nb] = Bs[(k0 + tig + 4) * 72 + nb * 8 + g];
            }
#pragma unroll
            for (int nb = 0; nb < 8; ++nb) {
                asm volatile(
                    "mma.sync.aligned.m16n8k8.row.col.f32.tf32.tf32.f32 "
                    "{%0,%1,%2,%3}, {%4,%5,%6,%7}, {%8,%9}, {%0,%1,%2,%3};"
                    : "+f"(c[nb][0]), "+f"(c[nb][1]), "+f"(c[nb][2]), "+f"(c[nb][3])
                    : "r"(ar0[kc]), "r"(ar1[kc]), "r"(ar2[kc]), "r"(ar3[kc]),
                      "r"(b0[nb]), "r"(b1[nb]));
            }
        }

        if (cb == selfcb) {
            float* C = (float*)cfg.outp[t][cb];
#pragma unroll
            for (int nb = 0; nb < 8; ++nb) {
                int col = nb * 8 + tig * 2;
                float b0v = __ldg(&bias[col]), b1v = __ldg(&bias[col + 1]);
                if (v0) __stcs((float2*)&C[(size_t)r0g * 64 + col],
                               make_float2(c[nb][0] + b0v, c[nb][1] + b1v));
                if (v1) __stcs((float2*)&C[(size_t)(r0g + 8) * 64 + col],
                               make_float2(c[nb][2] + b0v, c[nb][3] + b1v));
            }
        } else {
            unsigned* C = (unsigned*)cfg.outp[t][cb];
#pragma unroll
            for (int nb = 0; nb < 8; ++nb) {
                int u = nb * 4 + tig;  // uint column index (2 halves)
                if (v0) {
                    __half2 h = __float22half2_rn(make_float2(c[nb][0], c[nb][1]));
                    C[(size_t)r0g * 32 + u] = *(unsigned*)&h;
                }
                if (v1) {
                    __half2 h = __float22half2_rn(make_float2(c[nb][2], c[nb][3]));
                    C[(size_t)(r0g + 8) * 32 + u] = *(unsigned*)&h;
                }
            }
        }
    }
}

// ---------------- CSR accumulate + ReLU: warp per node, half2 per lane ----------------
__global__ __launch_bounds__(256) void accum_kernel(float2* __restrict__ out2) {
    int node = blockIdx.x * 8 + (threadIdx.x >> 5);
    if (node >= N_NODES) return;
    int l = threadIdx.x & 31;
    int s = g_off[node], e = g_off[node + 1];

    float2 acc = make_float2(0.f, 0.f);
    int i = s;
    for (; i + 3 < e; i += 4) {
        unsigned p0 = __ldcs(&g_perm[i]);
        unsigned p1 = __ldcs(&g_perm[i + 1]);
        unsigned p2 = __ldcs(&g_perm[i + 2]);
        unsigned p3 = __ldcs(&g_perm[i + 3]);
        unsigned u0 = __ldg(&g_y[(size_t)(p0 & 0xFFFFFu) * 32 + l]);
        unsigned u1 = __ldg(&g_y[(size_t)(p1 & 0xFFFFFu) * 32 + l]);
        unsigned u2 = __ldg(&g_y[(size_t)(p2 & 0xFFFFFu) * 32 + l]);
        unsigned u3 = __ldg(&g_y[(size_t)(p3 & 0xFFFFFu) * 32 + l]);
        float s0 = __uint_as_float(g_deg[c_SCALE_BASE[p0 >> 20] + node]);
        float s1 = __uint_as_float(g_deg[c_SCALE_BASE[p1 >> 20] + node]);
        float s2 = __uint_as_float(g_deg[c_SCALE_BASE[p2 >> 20] + node]);
        float s3 = __uint_as_float(g_deg[c_SCALE_BASE[p3 >> 20] + node]);
        float2 v0 = __half22float2(*(__half2*)&u0);
        float2 v1 = __half22float2(*(__half2*)&u1);
        float2 v2 = __half22float2(*(__half2*)&u2);
        float2 v3 = __half22float2(*(__half2*)&u3);
        acc.x += v0.x * s0 + v1.x * s1 + v2.x * s2 + v3.x * s3;
        acc.y += v0.y * s0 + v1.y * s1 + v2.y * s2 + v3.y * s3;
    }
    for (; i < e; ++i) {
        unsigned p = __ldcs(&g_perm[i]);
        unsigned u = __ldg(&g_y[(size_t)(p & 0xFFFFFu) * 32 + l]);
        float sc = __uint_as_float(g_deg[c_SCALE_BASE[p >> 20] + node]);
        float2 v = __half22float2(*(__half2*)&u);
        acc.x += v.x * sc;
        acc.y += v.y * sc;
    }

    float2 o = __ldcs(&out2[(size_t)node * 32 + l]);  // self-loop + bias from GEMM
    o.x = fmaxf(o.x + acc.x, 0.f);
    o.y = fmaxf(o.y + acc.y, 0.f);
    __stcs(&out2[(size_t)node * 32 + l], o);
}

// ---------------- launch ----------------
static cudaStream_t g_s2;
static cudaEvent_t  g_fork, g_es3, g_join;
static bool         g_streams_ready = false;

extern "C" void kernel_launch(void* const* d_in, const int* in_sizes, int n_in,
                              void* d_out, int out_size) {
    const float* x_author = (const float*)d_in[0];
    const float* x_field  = (const float*)d_in[1];
    const float* x_inst   = (const float*)d_in[2];
    const float* x_paper  = (const float*)d_in[3];
    const float* weight   = (const float*)d_in[4];
    const float* selfw    = (const float*)d_in[5];
    const float* bias     = (const float*)d_in[6];

    EdgeSet es;
    int total = 0;
    for (int r = 0; r < 7; r++) {
        es.src[r] = (const int*)d_in[7 + 2 * r];
        es.dst[r] = (const int*)d_in[8 + 2 * r];
        es.pre[r] = total;
        total += in_sizes[7 + 2 * r];
    }
    es.pre[7] = total;

    float* out = (float*)d_out;
    unsigned* yb;
    cudaGetSymbolAddress((void**)&yb, g_y);

    float* out_author = out;
    float* out_field  = out + (size_t)N_AUTHOR * 64;
    float* out_inst   = out + (size_t)(N_AUTHOR + N_FIELD) * 64;
    float* out_paper  = out + (size_t)(N_AUTHOR + N_FIELD + N_INST) * 64;

    if (!g_streams_ready) {  // first call is uncaptured; handles reused at capture
        cudaStreamCreateWithFlags(&g_s2, cudaStreamNonBlocking);
        cudaEventCreateWithFlags(&g_fork, cudaEventDisableTiming);
        cudaEventCreateWithFlags(&g_es3, cudaEventDisableTiming);
        cudaEventCreateWithFlags(&g_join, cudaEventDisableTiming);
        g_streams_ready = true;
    }

    // ---- fork ----
    cudaEventRecord(g_fork, 0);
    cudaStreamWaitEvent(g_s2, g_fork, 0);

    // launch order note: ncu (-s 5 -c 1) profiles the 4th kernel in code order.
    pack_w_kernel<<<ceil_div(90112, 256), 256, 0, g_s2>>>(weight, selfw);      // 0
    zero_kernel<<<ceil_div(858000, 256), 256>>>();                              // 1
    count_deg_kernel<<<ceil_div(total, 256), 256>>>(es);                        // 2

    GemmCfg cfg;
    cfg.A[0] = x_author; cfg.A[1] = x_paper; cfg.A[2] = x_field; cfg.A[3] = x_inst;
    cfg.M[0] = N_AUTHOR; cfg.M[1] = N_PAPER; cfg.M[2] = N_FIELD; cfg.M[3] = N_INST;
    cfg.wblk[0] = 0; cfg.wblk[1] = 3; cfg.wblk[2] = 7; cfg.wblk[3] = 9;
    cfg.nblk[0] = 3; cfg.nblk[1] = 4; cfg.nblk[2] = 2; cfg.nblk[3] = 2;
    cfg.selfcb[0] = 2; cfg.selfcb[1] = 3; cfg.selfcb[2] = 1; cfg.selfcb[3] = 1;
    cfg.outp[0][0] = yb;                         cfg.outp[0][1] = yb + (size_t)750000 * 32;
    cfg.outp[0][2] = out_author;                 cfg.outp[0][3] = nullptr;
    cfg.outp[1][0] = yb + (size_t)100000 * 32;   cfg.outp[1][1] = yb + (size_t)300000 * 32;
    cfg.outp[1][2] = yb + (size_t)500000 * 32;   cfg.outp[1][3] = out_paper;
    cfg.outp[2][0] = yb + (size_t)700000 * 32;   cfg.outp[2][1] = out_field;
    cfg.outp[2][2] = nullptr;                    cfg.outp[2][3] = nullptr;
    cfg.outp[3][0] = yb + (size_t)850000 * 32;   cfg.outp[3][1] = out_inst;
    cfg.outp[3][2] = nullptr;                    cfg.outp[3][3] = nullptr;
    cfg.pre[0] = 0;
    cfg.pre[1] = cfg.pre[0] + ceil_div(N_AUTHOR, 128);  // 782
    cfg.pre[2] = cfg.pre[1] + ceil_div(N_PAPER, 128);   // 2345
    cfg.pre[3] = cfg.pre[2] + ceil_div(N_FIELD, 128);   // 2736
    cfg.pre[4] = cfg.pre[3] + ceil_div(N_INST, 128);    // 2799
    gemm_kernel<<<cfg.pre[4], 256, 0, g_s2>>>(cfg, bias);                       // 3 <- profiled

    const int nchunks = ceil_div(N_NODES, 1024);  // 350
    scan1_kernel<<<nchunks, 256>>>();                                           // 4
    scan2_kernel<<<1, 512>>>(nchunks);                                          // 5
    scan3_kernel<<<nchunks, 1024>>>();                                          // 6
    cudaEventRecord(g_es3, 0);            // scans done reading raw counts
    cudaStreamWaitEvent(g_s2, g_es3, 0);
    inv_deg_kernel<<<ceil_div(858000, 256), 256, 0, g_s2>>>();                  // 7 (s2)
    place_kernel<<<ceil_div(total, 256), 256>>>(es);                            // 8 (main)
    cudaEventRecord(g_join, g_s2);

    // ---- join, then gather-sum + fused ReLU ----
    cudaStreamWaitEvent(0, g_join, 0);
    accum_kernel<<<ceil_div(N_NODES, 8), 256>>>((float2*)out);                  // 9
}